// round 8
// baseline (speedup 1.0000x reference)
#include <cuda_runtime.h>

#define N_NODES 100000
#define N_EDGES 1000000
#define N_GRAPHS 2048
#define SCAN_BS 512
#define SCAN_NB ((N_NODES + SCAN_BS - 1) / SCAN_BS)
// dynamic smem layout for k_conv2
#define SM_WL 0
#define SM_WR 16384
#define SM_B  32768
#define SM_MEAN 33024
#define MEAN_STRIDE 68
#define SMEM_CONV2 (33024 + 256 * MEAN_STRIDE * 4)

typedef unsigned long long u64;

// ---------------- device scratch (no allocs allowed) ----------------
__device__ float g_hA[N_NODES * 64];
__device__ float g_hB[N_NODES * 64];
__device__ float g_Ep[128 * 64];          // emb @ W1l  (32 KB, L1-resident)
__device__ float g_Rp[128 * 64];          // emb @ W1r
__device__ int   g_deg[N_NODES];          // INVARIANT: zero at kernel_launch entry
__device__ int   g_rowptr[N_NODES + 1];
__device__ int   g_cursor[N_NODES];
__device__ int   g_colsrc[N_EDGES];       // packed: src_node | (vocab_id << 20)
__device__ u64   g_lb[SCAN_NB];

// ---------------- f32x2 packed helpers ----------------
__device__ __forceinline__ u64 pk2(float x) {
    u64 r; asm("mov.b64 %0, {%1, %1};" : "=l"(r) : "f"(x)); return r;
}
__device__ __forceinline__ void fma2(u64 &d, u64 a, u64 b) {
    asm("fma.rn.f32x2 %0, %1, %2, %0;" : "+l"(d) : "l"(a), "l"(b));
}
__device__ __forceinline__ void add2(u64 &d, u64 a) {
    asm("add.rn.f32x2 %0, %0, %1;" : "+l"(d) : "l"(a));
}
__device__ __forceinline__ float2 up2(u64 v) {
    float lo, hi; asm("mov.b64 {%0, %1}, %2;" : "=f"(lo), "=f"(hi) : "l"(v));
    float2 f; f.x = lo; f.y = hi; return f;
}

// ---------- launch 1: E'=emb@W1l, R'=emb@W1r  +  dst histogram + lb reset ----
__global__ void k_prep(const float* __restrict__ emb, const float* __restrict__ W1l,
                       const float* __restrict__ W1r, const int* __restrict__ dst) {
    int b = blockIdx.x, t = threadIdx.x;
    if (b < 128) {
        __shared__ float se[64];
        if (b == 0) for (int i = t; i < SCAN_NB; i += 128) g_lb[i] = 0ULL;
        if (t < 64) se[t] = emb[b * 64 + t];
        __syncthreads();
        const float* W = (t < 64) ? W1l : W1r;
        int c = t & 63;
        float acc = 0.f;
#pragma unroll 8
        for (int k = 0; k < 64; k++) acc += se[k] * __ldg(W + k * 64 + c);
        if (t < 64) g_Ep[b * 64 + c] = acc; else g_Rp[b * 64 + c] = acc;
    } else {
        int base = (b - 128) * 512;                 // 512 edges per block
        int e0 = base + 2 * t;
        if (e0 < N_EDGES) atomicAdd(&g_deg[__ldg(dst + e0)], 1);
        if (e0 + 1 < N_EDGES) atomicAdd(&g_deg[__ldg(dst + e0 + 1)], 1);
    }
}

// ---------------- launch 2: single-pass decoupled-lookback scan -------------
__global__ void __launch_bounds__(SCAN_BS) k_scanlb() {
    __shared__ int s[SCAN_BS];
    __shared__ int s_prefix;
    int t = threadIdx.x, bid = blockIdx.x;
    int i = bid * SCAN_BS + t;
    int v = (i < N_NODES) ? g_deg[i] : 0;
    s[t] = v;
    __syncthreads();
    for (int off = 1; off < SCAN_BS; off <<= 1) {
        int x = (t >= off) ? s[t - off] : 0;
        __syncthreads();
        s[t] += x;
        __syncthreads();
    }
    int incl = s[t];
    int total = s[SCAN_BS - 1];
    if (t < 32) {
        unsigned prefix = 0;
        if (bid == 0) {
            if (t == 0) atomicExch(&g_lb[0], (2ULL << 32) | (unsigned)total);
        } else {
            if (t == 0) atomicExch(&g_lb[bid], (1ULL << 32) | (unsigned)total);
            int p = bid - 1;
            while (true) {
                int idx = p - t;
                u64 st = 0;
                if (idx >= 0) {
                    do { st = atomicAdd(&g_lb[idx], 0ULL); } while ((st >> 32) == 0);
                }
                unsigned pm = __ballot_sync(0xffffffffu, idx >= 0 && (st >> 32) == 2);
                unsigned val;
                if (pm) {
                    int closest = __ffs(pm) - 1;
                    val = (t <= closest) ? (unsigned)st : 0u;
                } else {
                    val = (idx >= 0) ? (unsigned)st : 0u;
                }
#pragma unroll
                for (int o = 16; o; o >>= 1) val += __shfl_xor_sync(0xffffffffu, val, o);
                prefix += val;
                if (pm) break;
                p -= 32;
            }
            if (t == 0) atomicExch(&g_lb[bid], (2ULL << 32) | (unsigned)(prefix + (unsigned)total));
        }
        if (t == 0) s_prefix = (int)prefix;
    }
    __syncthreads();
    int excl = incl - v + s_prefix;
    if (i < N_NODES) {
        g_rowptr[i] = excl;
        g_cursor[i] = excl;
        if (i == N_NODES - 1) g_rowptr[N_NODES] = excl + v;
    }
}

// ------- launch 3: CSR fill (packed node|vid) + restore deg invariant -------
__global__ void k_fill(const int* __restrict__ src, const int* __restrict__ dst,
                       const int* __restrict__ x) {
    int e = blockIdx.x * blockDim.x + threadIdx.x;
    if (e < N_NODES) g_deg[e] = 0;
    if (e >= N_EDGES) return;
    int sn = __ldg(src + e);
    int packed = sn | (__ldg(x + sn) << 20);
    int p = atomicAdd(&g_cursor[dst[e]], 1);
    g_colsrc[p] = packed;
}

// ---------------- aggregation core (f32x2 accumulate, 8 edges/iter) ---------
template <bool UseVid>
__device__ __forceinline__ void agg_core(const float* __restrict__ base,
                                         int s, int e, int half, int fb,
                                         u64 &A, u64 &B) {
    u64 a0 = 0, b0 = 0, a1 = 0, b1 = 0;
    int i = s;
    for (; i + 8 <= e; i += 8) {
        int u0 = __ldg(g_colsrc + i + half);
        int u1 = __ldg(g_colsrc + i + 2 + half);
        int u2 = __ldg(g_colsrc + i + 4 + half);
        int u3 = __ldg(g_colsrc + i + 6 + half);
        int r0 = UseVid ? (u0 >> 20) : (u0 & 0xFFFFF);
        int r1 = UseVid ? (u1 >> 20) : (u1 & 0xFFFFF);
        int r2 = UseVid ? (u2 >> 20) : (u2 & 0xFFFFF);
        int r3 = UseVid ? (u3 >> 20) : (u3 & 0xFFFFF);
        ulonglong2 v0 = *(const ulonglong2*)(base + r0 * 64 + fb);
        ulonglong2 v1 = *(const ulonglong2*)(base + r1 * 64 + fb);
        ulonglong2 v2 = *(const ulonglong2*)(base + r2 * 64 + fb);
        ulonglong2 v3 = *(const ulonglong2*)(base + r3 * 64 + fb);
        add2(a0, v0.x); add2(b0, v0.y);
        add2(a1, v1.x); add2(b1, v1.y);
        add2(a0, v2.x); add2(b0, v2.y);
        add2(a1, v3.x); add2(b1, v3.y);
    }
    for (; i + 2 <= e; i += 2) {
        int u = __ldg(g_colsrc + i + half);
        int r = UseVid ? (u >> 20) : (u & 0xFFFFF);
        ulonglong2 v = *(const ulonglong2*)(base + r * 64 + fb);
        add2(a0, v.x); add2(b0, v.y);
    }
    if (i < e && half == 0) {
        int u = __ldg(g_colsrc + i);
        int r = UseVid ? (u >> 20) : (u & 0xFFFFF);
        ulonglong2 v = *(const ulonglong2*)(base + r * 64 + fb);
        add2(a0, v.x); add2(b0, v.y);
    }
    add2(a0, a1); add2(b0, b1);
    u64 sa = __shfl_xor_sync(0xffffffffu, a0, 16);
    u64 sb = __shfl_xor_sync(0xffffffffu, b0, 16);
    add2(a0, sa); add2(b0, sb);
    A = a0; B = b0;
}

// launch 4 [capture slot]: conv1 fully fused — relu(mean(E'[vid]) + R'[x_n] + b1)
__global__ void k_agg1(const int* __restrict__ x, const float* __restrict__ b1,
                       float* __restrict__ out) {
    int w = (blockIdx.x * blockDim.x + threadIdx.x) >> 5;
    if (w >= N_NODES) return;
    int lane = threadIdx.x & 31;
    int half = lane >> 4;
    int fb = (lane & 15) * 4;
    int s = g_rowptr[w], e = g_rowptr[w + 1];
    u64 A, B;
    agg_core<true>(g_Ep, s, e, half, fb, A, B);
    if (half == 0) {
        float inv = __fdividef(1.f, (float)max(e - s, 1));
        float2 p = up2(A), q = up2(B);
        int vid = __ldg(x + w);
        float4 r = *(const float4*)(g_Rp + vid * 64 + fb);
        float4 bb = *(const float4*)(b1 + fb);
        float4 o;
        o.x = fmaxf(fmaf(p.x, inv, r.x + bb.x), 0.f);
        o.y = fmaxf(fmaf(p.y, inv, r.y + bb.y), 0.f);
        o.z = fmaxf(fmaf(q.x, inv, r.z + bb.z), 0.f);
        o.w = fmaxf(fmaf(q.y, inv, r.w + bb.w), 0.f);
        *(float4*)(out + w * 64 + fb) = o;
    }
}

// -------- launch 5: conv2 FUSED (agg -> smem -> dual GEMM + bias + relu) ----
// Block of 256 threads owns 256 nodes. Phase 1: 8 warps aggregate 32 nodes
// each into padded smem (stride 68 floats). Phase 2: thread-per-node dual
// GEMM with f32x2 accumulators, weights staged in smem.
__global__ void __launch_bounds__(256)
k_conv2(const float* __restrict__ h, const float* __restrict__ Wl,
        const float* __restrict__ Wr, const float* __restrict__ bias,
        float* __restrict__ out) {
    extern __shared__ char dsm[];
    ulonglong2* sWl = (ulonglong2*)(dsm + SM_WL);
    ulonglong2* sWr = (ulonglong2*)(dsm + SM_WR);
    u64*        sB  = (u64*)(dsm + SM_B);
    float*    sMean = (float*)(dsm + SM_MEAN);

    int t = threadIdx.x;
    const ulonglong2* gWl = (const ulonglong2*)Wl;
    const ulonglong2* gWr = (const ulonglong2*)Wr;
    for (int i = t; i < 1024; i += 256) { sWl[i] = gWl[i]; sWr[i] = gWr[i]; }
    if (t < 32) sB[t] = ((const u64*)bias)[t];

    // phase 1: aggregation into smem
    int wid = t >> 5, lane = t & 31;
    int half = lane >> 4;
    int fb = (lane & 15) * 4;
    int nbase = blockIdx.x * 256;
    for (int jj = 0; jj < 32; jj++) {
        int nl = wid * 32 + jj;
        int n = nbase + nl;
        if (n < N_NODES) {
            int s = g_rowptr[n], e = g_rowptr[n + 1];
            u64 A, B;
            agg_core<false>(h, s, e, half, fb, A, B);
            if (half == 0) {
                float inv = __fdividef(1.f, (float)max(e - s, 1));
                float2 p = up2(A), q = up2(B);
                float4 o; o.x = p.x * inv; o.y = p.y * inv; o.z = q.x * inv; o.w = q.y * inv;
                *(float4*)(sMean + nl * MEAN_STRIDE + fb) = o;
            }
        }
    }
    __syncthreads();

    // phase 2: dual GEMM
    int n = nbase + t;
    if (n >= N_NODES) return;
    u64 acc[32];
#pragma unroll
    for (int j = 0; j < 32; j++) acc[j] = sB[j];

    const float* am = sMean + t * MEAN_STRIDE;
    const float4* ah4 = (const float4*)(h + n * 64);
#pragma unroll 4
    for (int k0 = 0; k0 < 16; k0++) {
        float4 a4 = *(const float4*)(am + k0 * 4);
        float4 c4 = __ldg(ah4 + k0);
        float av[4] = {a4.x, a4.y, a4.z, a4.w};
        float cv[4] = {c4.x, c4.y, c4.z, c4.w};
#pragma unroll
        for (int kk = 0; kk < 4; kk++) {
            u64 a2 = pk2(av[kk]);
            u64 c2 = pk2(cv[kk]);
            const ulonglong2* wl = sWl + (k0 * 4 + kk) * 16;
            const ulonglong2* wr = sWr + (k0 * 4 + kk) * 16;
#pragma unroll
            for (int j = 0; j < 16; j++) {
                ulonglong2 l = wl[j], r = wr[j];
                fma2(acc[2 * j],     a2, l.x);
                fma2(acc[2 * j + 1], a2, l.y);
                fma2(acc[2 * j],     c2, r.x);
                fma2(acc[2 * j + 1], c2, r.y);
            }
        }
    }

    float4* o4 = (float4*)(out + n * 64);
#pragma unroll
    for (int j = 0; j < 16; j++) {
        float2 p = up2(acc[2 * j]);
        float2 q = up2(acc[2 * j + 1]);
        float4 o;
        o.x = fmaxf(p.x, 0.f); o.y = fmaxf(p.y, 0.f);
        o.z = fmaxf(q.x, 0.f); o.w = fmaxf(q.y, 0.f);
        o4[j] = o;
    }
}

// ---------------- launch 6: mean-pool + output head (warp per graph) --------
__global__ void k_pool(const float* __restrict__ h, const int* __restrict__ batch,
                       const float* __restrict__ Wout, const float* __restrict__ bout,
                       float* __restrict__ out) {
    int g = (blockIdx.x * blockDim.x + threadIdx.x) >> 5;
    if (g >= N_GRAPHS) return;
    int lane = threadIdx.x & 31;
    int s, e;
    { int lo = 0, hi = N_NODES;
      while (lo < hi) { int m = (lo + hi) >> 1; if (__ldg(batch + m) < g) lo = m + 1; else hi = m; }
      s = lo; }
    { int lo = s, hi = N_NODES;
      while (lo < hi) { int m = (lo + hi) >> 1; if (__ldg(batch + m) < g + 1) lo = m + 1; else hi = m; }
      e = lo; }
    float a0 = 0.f, a1 = 0.f;
#pragma unroll 4
    for (int n = s; n < e; ++n) {
        a0 += h[n * 64 + lane];
        a1 += h[n * 64 + lane + 32];
    }
    float inv = __fdividef(1.f, (float)max(e - s, 1));
    a0 *= inv; a1 *= inv;
    float p0 = a0 * __ldg(Wout + lane * 2 + 0) + a1 * __ldg(Wout + (lane + 32) * 2 + 0);
    float p1 = a0 * __ldg(Wout + lane * 2 + 1) + a1 * __ldg(Wout + (lane + 32) * 2 + 1);
#pragma unroll
    for (int off = 16; off; off >>= 1) {
        p0 += __shfl_xor_sync(0xffffffffu, p0, off);
        p1 += __shfl_xor_sync(0xffffffffu, p1, off);
    }
    if (lane == 0) {
        out[g * 2 + 0] = p0 + __ldg(bout + 0);
        out[g * 2 + 1] = p1 + __ldg(bout + 1);
    }
}

// ---------------- launch ----------------
extern "C" void kernel_launch(void* const* d_in, const int* in_sizes, int n_in,
                              void* d_out, int out_size) {
    const int*   x     = (const int*)d_in[0];
    const int*   ei    = (const int*)d_in[1];
    const int*   batch = (const int*)d_in[2];
    const float* emb   = (const float*)d_in[3];
    const float* W1l   = (const float*)d_in[4];
    const float* b1    = (const float*)d_in[5];
    const float* W1r   = (const float*)d_in[6];
    const float* W2l   = (const float*)d_in[7];
    const float* b2    = (const float*)d_in[8];
    const float* W2r   = (const float*)d_in[9];
    const float* Wo    = (const float*)d_in[10];
    const float* bo    = (const float*)d_in[11];
    const int* src = ei;
    const int* dst = ei + N_EDGES;
    float* out = (float*)d_out;

    float *hA, *hB;
    cudaGetSymbolAddress((void**)&hA, g_hA);
    cudaGetSymbolAddress((void**)&hB, g_hB);

    static bool attr_done = false;
    if (!attr_done) {
        cudaFuncSetAttribute(k_conv2, cudaFuncAttributeMaxDynamicSharedMemorySize,
                             SMEM_CONV2);
        attr_done = true;
    }

    // 1: weight transform + dst histogram + lb reset
    k_prep<<<128 + ((N_EDGES + 511) / 512), 256>>>(emb, W1l, W1r, dst);
    // 2: rowptr/cursor via lookback scan
    k_scanlb<<<SCAN_NB, SCAN_BS>>>();
    // 3: CSR fill, packed node|vid (+ restore deg==0)
    k_fill<<<(N_EDGES + 255) / 256, 256>>>(src, dst, x);

    // 4: conv1 fully fused (L1-resident E' gather)   <-- ncu capture slot
    k_agg1<<<(N_NODES * 32 + 255) / 256, 256>>>(x, b1, hB);

    // 5: conv2 fused agg + dual GEMM
    k_conv2<<<(N_NODES + 255) / 256, 256, SMEM_CONV2>>>(hB, W2l, W2r, b2, hA);

    // 6: pool + head
    k_pool<<<(N_GRAPHS * 32 + 255) / 256, 256>>>(hA, batch, Wo, bo, out);
}

// round 9
// speedup vs baseline: 1.2177x; 1.2177x over previous
#include <cuda_runtime.h>

#define N_NODES 100000
#define N_EDGES 1000000
#define N_GRAPHS 2048
#define SCAN_BS 512
#define SCAN_NB ((N_NODES + SCAN_BS - 1) / SCAN_BS)

typedef unsigned long long u64;

// ---------------- device scratch (no allocs allowed) ----------------
__device__ float g_hA[N_NODES * 64];
__device__ float g_hB[N_NODES * 64];
__device__ float g_mean[N_NODES * 64];
__device__ float g_Ep[128 * 64];          // emb @ W1l  (32 KB, L1-resident)
__device__ float g_Rp[128 * 64];          // emb @ W1r
__device__ int   g_deg[N_NODES];          // INVARIANT: zero at kernel_launch entry
__device__ int   g_rowptr[N_NODES + 1];
__device__ int   g_cursor[N_NODES];
__device__ int   g_colsrc[N_EDGES];       // packed: src_node | (vocab_id << 20)
__device__ u64   g_lb[SCAN_NB];

// ---------------- f32x2 packed helpers ----------------
__device__ __forceinline__ u64 pk2(float x) {
    u64 r; asm("mov.b64 %0, {%1, %1};" : "=l"(r) : "f"(x)); return r;
}
__device__ __forceinline__ void fma2(u64 &d, u64 a, u64 b) {
    asm("fma.rn.f32x2 %0, %1, %2, %0;" : "+l"(d) : "l"(a), "l"(b));
}
__device__ __forceinline__ void add2(u64 &d, u64 a) {
    asm("add.rn.f32x2 %0, %0, %1;" : "+l"(d) : "l"(a));
}
__device__ __forceinline__ float2 up2(u64 v) {
    float lo, hi; asm("mov.b64 {%0, %1}, %2;" : "=f"(lo), "=f"(hi) : "l"(v));
    float2 f; f.x = lo; f.y = hi; return f;
}

// ---------- launch 1: E'=emb@W1l, R'=emb@W1r  +  dst histogram + lb reset ----
__global__ void k_prep(const float* __restrict__ emb, const float* __restrict__ W1l,
                       const float* __restrict__ W1r, const int* __restrict__ dst) {
    int b = blockIdx.x, t = threadIdx.x;
    if (b < 128) {
        __shared__ float se[64];
        if (b == 0) for (int i = t; i < SCAN_NB; i += 128) g_lb[i] = 0ULL;
        if (t < 64) se[t] = emb[b * 64 + t];
        __syncthreads();
        const float* W = (t < 64) ? W1l : W1r;
        int c = t & 63;
        float acc = 0.f;
#pragma unroll 8
        for (int k = 0; k < 64; k++) acc += se[k] * __ldg(W + k * 64 + c);
        if (t < 64) g_Ep[b * 64 + c] = acc; else g_Rp[b * 64 + c] = acc;
    } else {
        int base = (b - 128) * 512;                 // 512 edges per block
        int e0 = base + 2 * t;
        if (e0 < N_EDGES) atomicAdd(&g_deg[__ldg(dst + e0)], 1);
        if (e0 + 1 < N_EDGES) atomicAdd(&g_deg[__ldg(dst + e0 + 1)], 1);
    }
}

// ---------------- launch 2: single-pass decoupled-lookback scan -------------
__global__ void __launch_bounds__(SCAN_BS) k_scanlb() {
    __shared__ int s[SCAN_BS];
    __shared__ int s_prefix;
    int t = threadIdx.x, bid = blockIdx.x;
    int i = bid * SCAN_BS + t;
    int v = (i < N_NODES) ? g_deg[i] : 0;
    s[t] = v;
    __syncthreads();
    for (int off = 1; off < SCAN_BS; off <<= 1) {
        int x = (t >= off) ? s[t - off] : 0;
        __syncthreads();
        s[t] += x;
        __syncthreads();
    }
    int incl = s[t];
    int total = s[SCAN_BS - 1];
    if (t < 32) {
        unsigned prefix = 0;
        if (bid == 0) {
            if (t == 0) atomicExch(&g_lb[0], (2ULL << 32) | (unsigned)total);
        } else {
            if (t == 0) atomicExch(&g_lb[bid], (1ULL << 32) | (unsigned)total);
            int p = bid - 1;
            while (true) {
                int idx = p - t;
                u64 st = 0;
                if (idx >= 0) {
                    do { st = atomicAdd(&g_lb[idx], 0ULL); } while ((st >> 32) == 0);
                }
                unsigned pm = __ballot_sync(0xffffffffu, idx >= 0 && (st >> 32) == 2);
                unsigned val;
                if (pm) {
                    int closest = __ffs(pm) - 1;
                    val = (t <= closest) ? (unsigned)st : 0u;
                } else {
                    val = (idx >= 0) ? (unsigned)st : 0u;
                }
#pragma unroll
                for (int o = 16; o; o >>= 1) val += __shfl_xor_sync(0xffffffffu, val, o);
                prefix += val;
                if (pm) break;
                p -= 32;
            }
            if (t == 0) atomicExch(&g_lb[bid], (2ULL << 32) | (unsigned)(prefix + (unsigned)total));
        }
        if (t == 0) s_prefix = (int)prefix;
    }
    __syncthreads();
    int excl = incl - v + s_prefix;
    if (i < N_NODES) {
        g_rowptr[i] = excl;
        g_cursor[i] = excl;
        if (i == N_NODES - 1) g_rowptr[N_NODES] = excl + v;
    }
}

// ------- launch 3: CSR fill (packed node|vid) + restore deg invariant -------
__global__ void k_fill(const int* __restrict__ src, const int* __restrict__ dst,
                       const int* __restrict__ x) {
    int e = blockIdx.x * blockDim.x + threadIdx.x;
    if (e < N_NODES) g_deg[e] = 0;
    if (e >= N_EDGES) return;
    int sn = __ldg(src + e);
    int packed = sn | (__ldg(x + sn) << 20);
    int p = atomicAdd(&g_cursor[dst[e]], 1);
    g_colsrc[p] = packed;
}

// ------- aggregation core: HALF-WARP per node, f32x2 accumulate -------------
// Each half-warp walks its own node's edge list; 16 lanes x float4 features.
template <bool UseVid>
__device__ __forceinline__ void agg_half(const float* __restrict__ base,
                                         int s, int cnt, int fb, u64 &A, u64 &B) {
    u64 a0 = 0, b0 = 0, a1 = 0, b1 = 0;
    int i = 0;
    for (; i + 2 <= cnt; i += 2) {
        int u0 = __ldg(g_colsrc + s + i);
        int u1 = __ldg(g_colsrc + s + i + 1);
        int r0 = UseVid ? (u0 >> 20) : (u0 & 0xFFFFF);
        int r1 = UseVid ? (u1 >> 20) : (u1 & 0xFFFFF);
        ulonglong2 v0 = *(const ulonglong2*)(base + r0 * 64 + fb);
        ulonglong2 v1 = *(const ulonglong2*)(base + r1 * 64 + fb);
        add2(a0, v0.x); add2(b0, v0.y);
        add2(a1, v1.x); add2(b1, v1.y);
    }
    if (i < cnt) {
        int u = __ldg(g_colsrc + s + i);
        int r = UseVid ? (u >> 20) : (u & 0xFFFFF);
        ulonglong2 v = *(const ulonglong2*)(base + r * 64 + fb);
        add2(a0, v.x); add2(b0, v.y);
    }
    add2(a0, a1); add2(b0, b1);
    A = a0; B = b0;
}

// launch 4 [capture slot]: conv1 fused — relu(mean(E'[vid]) + R'[x_n] + b1)
// Warp handles 2 nodes: lanes 0-15 -> node 2w, lanes 16-31 -> node 2w+1.
__global__ void k_agg1(const int* __restrict__ x, const float* __restrict__ b1,
                       float* __restrict__ out) {
    int w = (blockIdx.x * blockDim.x + threadIdx.x) >> 5;
    int lane = threadIdx.x & 31;
    int n = 2 * w + (lane >> 4);
    if (n >= N_NODES) return;
    int fb = (lane & 15) * 4;
    int s = g_rowptr[n], e = g_rowptr[n + 1];
    u64 A, B;
    agg_half<true>(g_Ep, s, e - s, fb, A, B);
    float inv = __fdividef(1.f, (float)max(e - s, 1));
    float2 p = up2(A), q = up2(B);
    int vid = __ldg(x + n);
    float4 r = *(const float4*)(g_Rp + vid * 64 + fb);
    float4 bb = *(const float4*)(b1 + fb);
    float4 o;
    o.x = fmaxf(fmaf(p.x, inv, r.x + bb.x), 0.f);
    o.y = fmaxf(fmaf(p.y, inv, r.y + bb.y), 0.f);
    o.z = fmaxf(fmaf(q.x, inv, r.z + bb.z), 0.f);
    o.w = fmaxf(fmaf(q.y, inv, r.w + bb.w), 0.f);
    *(float4*)(out + n * 64 + fb) = o;
}

// launch 5: conv2 aggregation (plain mean), 2 nodes per warp
__global__ void k_agg(const float* __restrict__ h, float* __restrict__ mean) {
    int w = (blockIdx.x * blockDim.x + threadIdx.x) >> 5;
    int lane = threadIdx.x & 31;
    int n = 2 * w + (lane >> 4);
    if (n >= N_NODES) return;
    int fb = (lane & 15) * 4;
    int s = g_rowptr[n], e = g_rowptr[n + 1];
    u64 A, B;
    agg_half<false>(h, s, e - s, fb, A, B);
    float inv = __fdividef(1.f, (float)max(e - s, 1));
    float2 p = up2(A), q = up2(B);
    float4 o; o.x = p.x * inv; o.y = p.y * inv; o.z = q.x * inv; o.w = q.y * inv;
    *(float4*)(mean + n * 64 + fb) = o;
}

// ---------------- launch 6: conv2 dual GEMM + bias + relu -------------------
__global__ void __launch_bounds__(256)
k_mm(const float* __restrict__ Am, const float* __restrict__ Ah,
     const float* __restrict__ Wl, const float* __restrict__ Wr,
     const float* __restrict__ bias, float* __restrict__ out) {
    __shared__ ulonglong2 sWl[64 * 16];
    __shared__ ulonglong2 sWr[64 * 16];
    __shared__ u64 sB[32];
    int t = threadIdx.x;
    const ulonglong2* gWl = (const ulonglong2*)Wl;
    const ulonglong2* gWr = (const ulonglong2*)Wr;
    for (int i = t; i < 1024; i += 256) { sWl[i] = gWl[i]; sWr[i] = gWr[i]; }
    if (t < 32) sB[t] = ((const u64*)bias)[t];
    __syncthreads();
    int n = blockIdx.x * 256 + t;
    if (n >= N_NODES) return;

    u64 acc[32];
#pragma unroll
    for (int j = 0; j < 32; j++) acc[j] = sB[j];

    const float4* am4 = (const float4*)(Am + n * 64);
    const float4* ah4 = (const float4*)(Ah + n * 64);
#pragma unroll 4
    for (int k0 = 0; k0 < 16; k0++) {
        float4 a4 = __ldg(am4 + k0);
        float4 c4 = __ldg(ah4 + k0);
        float av[4] = {a4.x, a4.y, a4.z, a4.w};
        float cv[4] = {c4.x, c4.y, c4.z, c4.w};
#pragma unroll
        for (int kk = 0; kk < 4; kk++) {
            u64 a2 = pk2(av[kk]);
            u64 c2 = pk2(cv[kk]);
            const ulonglong2* wl = sWl + (k0 * 4 + kk) * 16;
            const ulonglong2* wr = sWr + (k0 * 4 + kk) * 16;
#pragma unroll
            for (int j = 0; j < 16; j++) {
                ulonglong2 l = wl[j], r = wr[j];
                fma2(acc[2 * j],     a2, l.x);
                fma2(acc[2 * j + 1], a2, l.y);
                fma2(acc[2 * j],     c2, r.x);
                fma2(acc[2 * j + 1], c2, r.y);
            }
        }
    }

    float4* o4 = (float4*)(out + n * 64);
#pragma unroll
    for (int j = 0; j < 16; j++) {
        float2 p = up2(acc[2 * j]);
        float2 q = up2(acc[2 * j + 1]);
        float4 o;
        o.x = fmaxf(p.x, 0.f); o.y = fmaxf(p.y, 0.f);
        o.z = fmaxf(q.x, 0.f); o.w = fmaxf(q.y, 0.f);
        o4[j] = o;
    }
}

// ---------------- launch 7: mean-pool + output head (warp per graph) --------
__global__ void k_pool(const float* __restrict__ h, const int* __restrict__ batch,
                       const float* __restrict__ Wout, const float* __restrict__ bout,
                       float* __restrict__ out) {
    int g = (blockIdx.x * blockDim.x + threadIdx.x) >> 5;
    if (g >= N_GRAPHS) return;
    int lane = threadIdx.x & 31;
    int s, e;
    { int lo = 0, hi = N_NODES;
      while (lo < hi) { int m = (lo + hi) >> 1; if (__ldg(batch + m) < g) lo = m + 1; else hi = m; }
      s = lo; }
    { int lo = s, hi = N_NODES;
      while (lo < hi) { int m = (lo + hi) >> 1; if (__ldg(batch + m) < g + 1) lo = m + 1; else hi = m; }
      e = lo; }
    float a0 = 0.f, a1 = 0.f;
#pragma unroll 4
    for (int n = s; n < e; ++n) {
        a0 += h[n * 64 + lane];
        a1 += h[n * 64 + lane + 32];
    }
    float inv = __fdividef(1.f, (float)max(e - s, 1));
    a0 *= inv; a1 *= inv;
    float p0 = a0 * __ldg(Wout + lane * 2 + 0) + a1 * __ldg(Wout + (lane + 32) * 2 + 0);
    float p1 = a0 * __ldg(Wout + lane * 2 + 1) + a1 * __ldg(Wout + (lane + 32) * 2 + 1);
#pragma unroll
    for (int off = 16; off; off >>= 1) {
        p0 += __shfl_xor_sync(0xffffffffu, p0, off);
        p1 += __shfl_xor_sync(0xffffffffu, p1, off);
    }
    if (lane == 0) {
        out[g * 2 + 0] = p0 + __ldg(bout + 0);
        out[g * 2 + 1] = p1 + __ldg(bout + 1);
    }
}

// ---------------- launch ----------------
extern "C" void kernel_launch(void* const* d_in, const int* in_sizes, int n_in,
                              void* d_out, int out_size) {
    const int*   x     = (const int*)d_in[0];
    const int*   ei    = (const int*)d_in[1];
    const int*   batch = (const int*)d_in[2];
    const float* emb   = (const float*)d_in[3];
    const float* W1l   = (const float*)d_in[4];
    const float* b1    = (const float*)d_in[5];
    const float* W1r   = (const float*)d_in[6];
    const float* W2l   = (const float*)d_in[7];
    const float* b2    = (const float*)d_in[8];
    const float* W2r   = (const float*)d_in[9];
    const float* Wo    = (const float*)d_in[10];
    const float* bo    = (const float*)d_in[11];
    const int* src = ei;
    const int* dst = ei + N_EDGES;
    float* out = (float*)d_out;

    float *hA, *hB, *mean;
    cudaGetSymbolAddress((void**)&hA, g_hA);
    cudaGetSymbolAddress((void**)&hB, g_hB);
    cudaGetSymbolAddress((void**)&mean, g_mean);

    // warps = ceil(N_NODES/2); threads = warps*32
    const int aggBlocks = ((N_NODES + 1) / 2 * 32 + 255) / 256;

    // 1: weight transform + dst histogram + lb reset
    k_prep<<<128 + ((N_EDGES + 511) / 512), 256>>>(emb, W1l, W1r, dst);
    // 2: rowptr/cursor via lookback scan
    k_scanlb<<<SCAN_NB, SCAN_BS>>>();
    // 3: CSR fill, packed node|vid (+ restore deg==0)
    k_fill<<<(N_EDGES + 255) / 256, 256>>>(src, dst, x);

    // 4: conv1 fused, 2 nodes/warp (L1-resident E')   <-- ncu capture slot
    k_agg1<<<aggBlocks, 256>>>(x, b1, hB);

    // 5-6: conv2
    k_agg<<<aggBlocks, 256>>>(hB, mean);
    k_mm<<<(N_NODES + 255) / 256, 256>>>(mean, hB, W2l, W2r, b2, hA);

    // 7: pool + head
    k_pool<<<(N_GRAPHS * 32 + 255) / 256, 256>>>(hA, batch, Wo, bo, out);
}

// round 10
// speedup vs baseline: 1.2760x; 1.0479x over previous
#include <cuda_runtime.h>
#include <cuda_fp16.h>

#define N_NODES 100000
#define N_EDGES 1000000
#define N_GRAPHS 2048
#define SCAN_BS 512
#define SCAN_NB ((N_NODES + SCAN_BS - 1) / SCAN_BS)

typedef unsigned long long u64;

// ---------------- device scratch (no allocs allowed) ----------------
__device__ float  g_hA[N_NODES * 64];
__device__ __half g_hBh[N_NODES * 64];    // conv1 output, fp16 (halved agg traffic)
__device__ float  g_mean[N_NODES * 64];
__device__ __half g_EpH[128 * 64];        // emb @ W1l, fp16 (16 KB, L1-resident)
__device__ float  g_Rp[128 * 64];         // emb @ W1r, fp32
__device__ int    g_deg[N_NODES];         // INVARIANT: zero at kernel_launch entry
__device__ int    g_rowptr[N_NODES + 1];
__device__ int    g_cursor[N_NODES];
__device__ int    g_colsrc[N_EDGES];      // packed: src_node | (vocab_id << 20)
__device__ u64    g_lb[SCAN_NB];

// ---------------- packed helpers ----------------
__device__ __forceinline__ u64 pk2(float x) {
    u64 r; asm("mov.b64 %0, {%1, %1};" : "=l"(r) : "f"(x)); return r;
}
__device__ __forceinline__ void fma2(u64 &d, u64 a, u64 b) {
    asm("fma.rn.f32x2 %0, %1, %2, %0;" : "+l"(d) : "l"(a), "l"(b));
}
__device__ __forceinline__ void add2(u64 &d, u64 a) {
    asm("add.rn.f32x2 %0, %0, %1;" : "+l"(d) : "l"(a));
}
__device__ __forceinline__ float2 up2(u64 v) {
    float lo, hi; asm("mov.b64 {%0, %1}, %2;" : "=f"(lo), "=f"(hi) : "l"(v));
    float2 f; f.x = lo; f.y = hi; return f;
}
// half2 (as u32) -> packed f32x2 (as u64)
__device__ __forceinline__ u64 h2f2(unsigned h) {
    u64 r;
    asm("{\n\t.reg .b16 l16, h16;\n\t.reg .f32 lo, hi;\n\t"
        "mov.b32 {l16, h16}, %1;\n\t"
        "cvt.f32.f16 lo, l16;\n\t"
        "cvt.f32.f16 hi, h16;\n\t"
        "mov.b64 %0, {lo, hi};\n\t}"
        : "=l"(r) : "r"(h));
    return r;
}

// ---------- launch 1: E'(fp16), R'(fp32)  +  dst histogram + lb reset -------
__global__ void k_prep(const float* __restrict__ emb, const float* __restrict__ W1l,
                       const float* __restrict__ W1r, const int* __restrict__ dst) {
    int b = blockIdx.x, t = threadIdx.x;
    if (b < 128) {
        __shared__ float se[64];
        if (b == 0) for (int i = t; i < SCAN_NB; i += 128) g_lb[i] = 0ULL;
        if (t < 64) se[t] = emb[b * 64 + t];
        __syncthreads();
        const float* W = (t < 64) ? W1l : W1r;
        int c = t & 63;
        float acc = 0.f;
#pragma unroll 8
        for (int k = 0; k < 64; k++) acc += se[k] * __ldg(W + k * 64 + c);
        if (t < 64) g_EpH[b * 64 + c] = __float2half_rn(acc);
        else        g_Rp[b * 64 + c] = acc;
    } else {
        int base = (b - 128) * 512;                 // 512 edges per block
        int e0 = base + 2 * t;
        if (e0 < N_EDGES) atomicAdd(&g_deg[__ldg(dst + e0)], 1);
        if (e0 + 1 < N_EDGES) atomicAdd(&g_deg[__ldg(dst + e0 + 1)], 1);
    }
}

// ---------------- launch 2: single-pass decoupled-lookback scan -------------
__global__ void __launch_bounds__(SCAN_BS) k_scanlb() {
    __shared__ int s[SCAN_BS];
    __shared__ int s_prefix;
    int t = threadIdx.x, bid = blockIdx.x;
    int i = bid * SCAN_BS + t;
    int v = (i < N_NODES) ? g_deg[i] : 0;
    s[t] = v;
    __syncthreads();
    for (int off = 1; off < SCAN_BS; off <<= 1) {
        int x = (t >= off) ? s[t - off] : 0;
        __syncthreads();
        s[t] += x;
        __syncthreads();
    }
    int incl = s[t];
    int total = s[SCAN_BS - 1];
    if (t < 32) {
        unsigned prefix = 0;
        if (bid == 0) {
            if (t == 0) atomicExch(&g_lb[0], (2ULL << 32) | (unsigned)total);
        } else {
            if (t == 0) atomicExch(&g_lb[bid], (1ULL << 32) | (unsigned)total);
            int p = bid - 1;
            while (true) {
                int idx = p - t;
                u64 st = 0;
                if (idx >= 0) {
                    do { st = atomicAdd(&g_lb[idx], 0ULL); } while ((st >> 32) == 0);
                }
                unsigned pm = __ballot_sync(0xffffffffu, idx >= 0 && (st >> 32) == 2);
                unsigned val;
                if (pm) {
                    int closest = __ffs(pm) - 1;
                    val = (t <= closest) ? (unsigned)st : 0u;
                } else {
                    val = (idx >= 0) ? (unsigned)st : 0u;
                }
#pragma unroll
                for (int o = 16; o; o >>= 1) val += __shfl_xor_sync(0xffffffffu, val, o);
                prefix += val;
                if (pm) break;
                p -= 32;
            }
            if (t == 0) atomicExch(&g_lb[bid], (2ULL << 32) | (unsigned)(prefix + (unsigned)total));
        }
        if (t == 0) s_prefix = (int)prefix;
    }
    __syncthreads();
    int excl = incl - v + s_prefix;
    if (i < N_NODES) {
        g_rowptr[i] = excl;
        g_cursor[i] = excl;
        if (i == N_NODES - 1) g_rowptr[N_NODES] = excl + v;
    }
}

// ------- launch 3: CSR fill (packed node|vid) + restore deg invariant -------
__global__ void k_fill(const int* __restrict__ src, const int* __restrict__ dst,
                       const int* __restrict__ x) {
    int e = blockIdx.x * blockDim.x + threadIdx.x;
    if (e < N_NODES) g_deg[e] = 0;
    if (e >= N_EDGES) return;
    int sn = __ldg(src + e);
    int packed = sn | (__ldg(x + sn) << 20);
    int p = atomicAdd(&g_cursor[dst[e]], 1);
    g_colsrc[p] = packed;
}

// launch 4 [capture slot]: conv1 fused, 2 nodes/warp, fp16 E' gather,
// fp16 hB output.  out = relu(mean(E'[vid]) + R'[x_n] + b1)
__global__ void k_agg1(const int* __restrict__ x, const float* __restrict__ b1) {
    int w = (blockIdx.x * blockDim.x + threadIdx.x) >> 5;
    int lane = threadIdx.x & 31;
    int n = 2 * w + (lane >> 4);
    if (n >= N_NODES) return;
    int sub = lane & 15;                       // uint2 (8B) slot within 128B row
    int s = g_rowptr[n], e = g_rowptr[n + 1];
    int cnt = e - s;
    const uint2* ep = (const uint2*)g_EpH;     // row = 16 uint2
    u64 A = 0, B = 0, A1 = 0, B1 = 0;
    int i = 0;
    for (; i + 2 <= cnt; i += 2) {
        int u0 = __ldg(g_colsrc + s + i);
        int u1 = __ldg(g_colsrc + s + i + 1);
        uint2 v0 = __ldg(ep + (u0 >> 20) * 16 + sub);
        uint2 v1 = __ldg(ep + (u1 >> 20) * 16 + sub);
        add2(A, h2f2(v0.x)); add2(B, h2f2(v0.y));
        add2(A1, h2f2(v1.x)); add2(B1, h2f2(v1.y));
    }
    if (i < cnt) {
        int u = __ldg(g_colsrc + s + i);
        uint2 v = __ldg(ep + (u >> 20) * 16 + sub);
        add2(A, h2f2(v.x)); add2(B, h2f2(v.y));
    }
    add2(A, A1); add2(B, B1);
    float inv = __fdividef(1.f, (float)max(cnt, 1));
    float2 p = up2(A), q = up2(B);
    int vid = __ldg(x + n);
    float4 r = *(const float4*)(g_Rp + vid * 64 + sub * 4);
    float4 bb = *(const float4*)(b1 + sub * 4);
    float o0 = fmaxf(fmaf(p.x, inv, r.x + bb.x), 0.f);
    float o1 = fmaxf(fmaf(p.y, inv, r.y + bb.y), 0.f);
    float o2 = fmaxf(fmaf(q.x, inv, r.z + bb.z), 0.f);
    float o3 = fmaxf(fmaf(q.y, inv, r.w + bb.w), 0.f);
    __half2 h0 = __floats2half2_rn(o0, o1);
    __half2 h1 = __floats2half2_rn(o2, o3);
    uint2 st; st.x = *(unsigned*)&h0; st.y = *(unsigned*)&h1;
    *((uint2*)g_hBh + n * 16 + sub) = st;
}

// launch 5: conv2 aggregation — warp per node, half-warp per edge, fp16 rows
__global__ void k_agg(float* __restrict__ mean) {
    int n = (blockIdx.x * blockDim.x + threadIdx.x) >> 5;
    if (n >= N_NODES) return;
    int lane = threadIdx.x & 31;
    int half = lane >> 4;
    int sub = lane & 15;
    int s = g_rowptr[n], e = g_rowptr[n + 1];
    const uint2* hb = (const uint2*)g_hBh;
    u64 A = 0, B = 0, A1 = 0, B1 = 0;
    int i = s;
    for (; i + 4 <= e; i += 4) {
        int u0 = __ldg(g_colsrc + i + half);
        int u1 = __ldg(g_colsrc + i + 2 + half);
        uint2 v0 = __ldg(hb + (u0 & 0xFFFFF) * 16 + sub);
        uint2 v1 = __ldg(hb + (u1 & 0xFFFFF) * 16 + sub);
        add2(A, h2f2(v0.x)); add2(B, h2f2(v0.y));
        add2(A1, h2f2(v1.x)); add2(B1, h2f2(v1.y));
    }
    if (i + 2 <= e) {
        int u = __ldg(g_colsrc + i + half);
        uint2 v = __ldg(hb + (u & 0xFFFFF) * 16 + sub);
        add2(A, h2f2(v.x)); add2(B, h2f2(v.y));
        i += 2;
    }
    if (i < e && half == 0) {
        int u = __ldg(g_colsrc + i);
        uint2 v = __ldg(hb + (u & 0xFFFFF) * 16 + sub);
        add2(A, h2f2(v.x)); add2(B, h2f2(v.y));
    }
    add2(A, A1); add2(B, B1);
    u64 sa = __shfl_xor_sync(0xffffffffu, A, 16);
    u64 sb = __shfl_xor_sync(0xffffffffu, B, 16);
    add2(A, sa); add2(B, sb);
    if (half == 0) {
        float inv = __fdividef(1.f, (float)max(e - s, 1));
        float2 p = up2(A), q = up2(B);
        float4 o; o.x = p.x * inv; o.y = p.y * inv; o.z = q.x * inv; o.w = q.y * inv;
        *(float4*)(mean + n * 64 + sub * 4) = o;
    }
}

// ---------------- launch 6: conv2 dual GEMM + bias + relu -------------------
__global__ void __launch_bounds__(256)
k_mm(const float* __restrict__ Am, const float* __restrict__ Wl,
     const float* __restrict__ Wr, const float* __restrict__ bias,
     float* __restrict__ out) {
    __shared__ ulonglong2 sWl[64 * 16];
    __shared__ ulonglong2 sWr[64 * 16];
    __shared__ u64 sB[32];
    int t = threadIdx.x;
    const ulonglong2* gWl = (const ulonglong2*)Wl;
    const ulonglong2* gWr = (const ulonglong2*)Wr;
    for (int i = t; i < 1024; i += 256) { sWl[i] = gWl[i]; sWr[i] = gWr[i]; }
    if (t < 32) sB[t] = ((const u64*)bias)[t];
    __syncthreads();
    int n = blockIdx.x * 256 + t;
    if (n >= N_NODES) return;

    u64 acc[32];
#pragma unroll
    for (int j = 0; j < 32; j++) acc[j] = sB[j];

    const float4* am4 = (const float4*)(Am + n * 64);
    const uint2*  ah2 = (const uint2*)g_hBh + n * 16;
#pragma unroll 4
    for (int k0 = 0; k0 < 16; k0++) {
        float4 a4 = __ldg(am4 + k0);
        uint2 cc = __ldg(ah2 + k0);
        float2 c01 = up2(h2f2(cc.x));
        float2 c23 = up2(h2f2(cc.y));
        float av[4] = {a4.x, a4.y, a4.z, a4.w};
        float cv[4] = {c01.x, c01.y, c23.x, c23.y};
#pragma unroll
        for (int kk = 0; kk < 4; kk++) {
            u64 a2 = pk2(av[kk]);
            u64 c2 = pk2(cv[kk]);
            const ulonglong2* wl = sWl + (k0 * 4 + kk) * 16;
            const ulonglong2* wr = sWr + (k0 * 4 + kk) * 16;
#pragma unroll
            for (int j = 0; j < 16; j++) {
                ulonglong2 l = wl[j], r = wr[j];
                fma2(acc[2 * j],     a2, l.x);
                fma2(acc[2 * j + 1], a2, l.y);
                fma2(acc[2 * j],     c2, r.x);
                fma2(acc[2 * j + 1], c2, r.y);
            }
        }
    }

    float4* o4 = (float4*)(out + n * 64);
#pragma unroll
    for (int j = 0; j < 16; j++) {
        float2 p = up2(acc[2 * j]);
        float2 q = up2(acc[2 * j + 1]);
        float4 o;
        o.x = fmaxf(p.x, 0.f); o.y = fmaxf(p.y, 0.f);
        o.z = fmaxf(q.x, 0.f); o.w = fmaxf(q.y, 0.f);
        o4[j] = o;
    }
}

// ---------------- launch 7: mean-pool + output head (warp per graph) --------
__global__ void k_pool(const float* __restrict__ h, const int* __restrict__ batch,
                       const float* __restrict__ Wout, const float* __restrict__ bout,
                       float* __restrict__ out) {
    int g = (blockIdx.x * blockDim.x + threadIdx.x) >> 5;
    if (g >= N_GRAPHS) return;
    int lane = threadIdx.x & 31;
    int s, e;
    { int lo = 0, hi = N_NODES;
      while (lo < hi) { int m = (lo + hi) >> 1; if (__ldg(batch + m) < g) lo = m + 1; else hi = m; }
      s = lo; }
    { int lo = s, hi = N_NODES;
      while (lo < hi) { int m = (lo + hi) >> 1; if (__ldg(batch + m) < g + 1) lo = m + 1; else hi = m; }
      e = lo; }
    float a0 = 0.f, a1 = 0.f;
#pragma unroll 4
    for (int n = s; n < e; ++n) {
        a0 += h[n * 64 + lane];
        a1 += h[n * 64 + lane + 32];
    }
    float inv = __fdividef(1.f, (float)max(e - s, 1));
    a0 *= inv; a1 *= inv;
    float p0 = a0 * __ldg(Wout + lane * 2 + 0) + a1 * __ldg(Wout + (lane + 32) * 2 + 0);
    float p1 = a0 * __ldg(Wout + lane * 2 + 1) + a1 * __ldg(Wout + (lane + 32) * 2 + 1);
#pragma unroll
    for (int off = 16; off; off >>= 1) {
        p0 += __shfl_xor_sync(0xffffffffu, p0, off);
        p1 += __shfl_xor_sync(0xffffffffu, p1, off);
    }
    if (lane == 0) {
        out[g * 2 + 0] = p0 + __ldg(bout + 0);
        out[g * 2 + 1] = p1 + __ldg(bout + 1);
    }
}

// ---------------- launch ----------------
extern "C" void kernel_launch(void* const* d_in, const int* in_sizes, int n_in,
                              void* d_out, int out_size) {
    const int*   x     = (const int*)d_in[0];
    const int*   ei    = (const int*)d_in[1];
    const int*   batch = (const int*)d_in[2];
    const float* emb   = (const float*)d_in[3];
    const float* W1l   = (const float*)d_in[4];
    const float* b1    = (const float*)d_in[5];
    const float* W1r   = (const float*)d_in[6];
    const float* W2l   = (const float*)d_in[7];
    const float* b2    = (const float*)d_in[8];
    const float* W2r   = (const float*)d_in[9];
    const float* Wo    = (const float*)d_in[10];
    const float* bo    = (const float*)d_in[11];
    const int* src = ei;
    const int* dst = ei + N_EDGES;
    float* out = (float*)d_out;

    float *hA, *mean;
    cudaGetSymbolAddress((void**)&hA, g_hA);
    cudaGetSymbolAddress((void**)&mean, g_mean);

    const int agg1Blocks = ((N_NODES + 1) / 2 * 32 + 255) / 256;   // 2 nodes/warp
    const int aggBlocks  = (N_NODES * 32 + 255) / 256;             // warp/node

    // 1: weight transform (E' fp16, R' fp32) + dst histogram + lb reset
    k_prep<<<128 + ((N_EDGES + 511) / 512), 256>>>(emb, W1l, W1r, dst);
    // 2: rowptr/cursor via lookback scan
    k_scanlb<<<SCAN_NB, SCAN_BS>>>();
    // 3: CSR fill, packed node|vid (+ restore deg==0)
    k_fill<<<(N_EDGES + 255) / 256, 256>>>(src, dst, x);

    // 4: conv1 fused (fp16 E' gather -> fp16 hB)   <-- ncu capture slot
    k_agg1<<<agg1Blocks, 256>>>(x, b1);

    // 5-6: conv2 (fp16 gather -> fp32 mean; GEMM reads fp16 h + fp32 mean)
    k_agg<<<aggBlocks, 256>>>(mean);
    k_mm<<<(N_NODES + 255) / 256, 256>>>(mean, W2l, W2r, b2, hA);

    // 7: pool + head
    k_pool<<<(N_GRAPHS * 32 + 255) / 256, 256>>>(hA, batch, Wo, bo, out);
}

// round 11
// speedup vs baseline: 1.3386x; 1.0490x over previous
#include <cuda_runtime.h>
#include <cuda_fp16.h>

#define N_NODES 100000
#define N_EDGES 1000000
#define N_GRAPHS 2048
#define SCAN_BS 512
#define SCAN_NB ((N_NODES + SCAN_BS - 1) / SCAN_BS)

typedef unsigned long long u64;

// ---------------- device scratch (no allocs allowed) ----------------
__device__ float  g_hA[N_NODES * 64];
__device__ __half g_hBh[N_NODES * 64];    // conv1 output, fp16
__device__ float  g_mean[N_NODES * 64];
__device__ __half g_EpH[128 * 64];        // emb @ W1l, fp16 (16 KB, L1-resident)
__device__ float  g_Rp[128 * 64];         // emb @ W1r, fp32
__device__ int    g_deg[N_NODES];         // INVARIANT: zero at kernel_launch entry
__device__ int    g_rowptr[N_NODES + 1];
__device__ int    g_cursor[N_NODES];
__device__ int    g_colsrc[N_EDGES];      // packed: src_node | (vocab_id << 20)
__device__ u64    g_lb[SCAN_NB];

// ---------------- packed helpers ----------------
__device__ __forceinline__ u64 pk2(float x) {
    u64 r; asm("mov.b64 %0, {%1, %1};" : "=l"(r) : "f"(x)); return r;
}
__device__ __forceinline__ void fma2(u64 &d, u64 a, u64 b) {
    asm("fma.rn.f32x2 %0, %1, %2, %0;" : "+l"(d) : "l"(a), "l"(b));
}
__device__ __forceinline__ float2 up2(u64 v) {
    float lo, hi; asm("mov.b64 {%0, %1}, %2;" : "=f"(lo), "=f"(hi) : "l"(v));
    float2 f; f.x = lo; f.y = hi; return f;
}
// fp16x2 accumulate (HADD2, 1 instruction)
__device__ __forceinline__ void hadd2(unsigned &d, unsigned a) {
    asm("add.rn.f16x2 %0, %0, %1;" : "+r"(d) : "r"(a));
}
__device__ __forceinline__ float2 h2f(unsigned h) {
    __half2 v = *reinterpret_cast<__half2*>(&h);
    return __half22float2(v);
}
// half2 (as u32) -> packed f32x2 (as u64)   (k_mm only, cold path)
__device__ __forceinline__ u64 h2f2(unsigned h) {
    u64 r;
    asm("{\n\t.reg .b16 l16, h16;\n\t.reg .f32 lo, hi;\n\t"
        "mov.b32 {l16, h16}, %1;\n\t"
        "cvt.f32.f16 lo, l16;\n\t"
        "cvt.f32.f16 hi, h16;\n\t"
        "mov.b64 %0, {lo, hi};\n\t}"
        : "=l"(r) : "r"(h));
    return r;
}

// ---------- launch 1: E'(fp16), R'(fp32)  +  dst histogram + lb reset -------
__global__ void k_prep(const float* __restrict__ emb, const float* __restrict__ W1l,
                       const float* __restrict__ W1r, const int* __restrict__ dst) {
    int b = blockIdx.x, t = threadIdx.x;
    if (b < 128) {
        __shared__ float se[64];
        if (b == 0) for (int i = t; i < SCAN_NB; i += 128) g_lb[i] = 0ULL;
        if (t < 64) se[t] = emb[b * 64 + t];
        __syncthreads();
        const float* W = (t < 64) ? W1l : W1r;
        int c = t & 63;
        float acc = 0.f;
#pragma unroll 8
        for (int k = 0; k < 64; k++) acc += se[k] * __ldg(W + k * 64 + c);
        if (t < 64) g_EpH[b * 64 + c] = __float2half_rn(acc);
        else        g_Rp[b * 64 + c] = acc;
    } else {
        int base = (b - 128) * 512;                 // 512 edges per block
        int e0 = base + 2 * t;
        if (e0 < N_EDGES) atomicAdd(&g_deg[__ldg(dst + e0)], 1);
        if (e0 + 1 < N_EDGES) atomicAdd(&g_deg[__ldg(dst + e0 + 1)], 1);
    }
}

// ---------------- launch 2: single-pass decoupled-lookback scan -------------
__global__ void __launch_bounds__(SCAN_BS) k_scanlb() {
    __shared__ int s[SCAN_BS];
    __shared__ int s_prefix;
    int t = threadIdx.x, bid = blockIdx.x;
    int i = bid * SCAN_BS + t;
    int v = (i < N_NODES) ? g_deg[i] : 0;
    s[t] = v;
    __syncthreads();
    for (int off = 1; off < SCAN_BS; off <<= 1) {
        int x = (t >= off) ? s[t - off] : 0;
        __syncthreads();
        s[t] += x;
        __syncthreads();
    }
    int incl = s[t];
    int total = s[SCAN_BS - 1];
    if (t < 32) {
        unsigned prefix = 0;
        if (bid == 0) {
            if (t == 0) atomicExch(&g_lb[0], (2ULL << 32) | (unsigned)total);
        } else {
            if (t == 0) atomicExch(&g_lb[bid], (1ULL << 32) | (unsigned)total);
            int p = bid - 1;
            while (true) {
                int idx = p - t;
                u64 st = 0;
                if (idx >= 0) {
                    do { st = atomicAdd(&g_lb[idx], 0ULL); } while ((st >> 32) == 0);
                }
                unsigned pm = __ballot_sync(0xffffffffu, idx >= 0 && (st >> 32) == 2);
                unsigned val;
                if (pm) {
                    int closest = __ffs(pm) - 1;
                    val = (t <= closest) ? (unsigned)st : 0u;
                } else {
                    val = (idx >= 0) ? (unsigned)st : 0u;
                }
#pragma unroll
                for (int o = 16; o; o >>= 1) val += __shfl_xor_sync(0xffffffffu, val, o);
                prefix += val;
                if (pm) break;
                p -= 32;
            }
            if (t == 0) atomicExch(&g_lb[bid], (2ULL << 32) | (unsigned)(prefix + (unsigned)total));
        }
        if (t == 0) s_prefix = (int)prefix;
    }
    __syncthreads();
    int excl = incl - v + s_prefix;
    if (i < N_NODES) {
        g_rowptr[i] = excl;
        g_cursor[i] = excl;
        if (i == N_NODES - 1) g_rowptr[N_NODES] = excl + v;
    }
}

// ------- launch 3: CSR fill (packed node|vid) + restore deg invariant -------
__global__ void k_fill(const int* __restrict__ src, const int* __restrict__ dst,
                       const int* __restrict__ x) {
    int e = blockIdx.x * blockDim.x + threadIdx.x;
    if (e < N_NODES) g_deg[e] = 0;
    if (e >= N_EDGES) return;
    int sn = __ldg(src + e);
    int packed = sn | (__ldg(x + sn) << 20);
    int p = atomicAdd(&g_cursor[dst[e]], 1);
    g_colsrc[p] = packed;
}

// launch 4 [capture slot]: conv1 fused, 2 nodes/warp, fp16 gather + HADD2 accum
// out = relu(mean(E'[vid]) + R'[x_n] + b1)  -> fp16 hB
__global__ void k_agg1(const int* __restrict__ x, const float* __restrict__ b1) {
    int w = (blockIdx.x * blockDim.x + threadIdx.x) >> 5;
    int lane = threadIdx.x & 31;
    int n = 2 * w + (lane >> 4);
    if (n >= N_NODES) return;
    int sub = lane & 15;                       // uint2 (8B) slot within 128B row
    int s = g_rowptr[n], e = g_rowptr[n + 1];
    int cnt = e - s;
    const uint2* ep = (const uint2*)g_EpH;     // row = 16 uint2
    unsigned A0 = 0, B0 = 0, A1 = 0, B1 = 0;   // half2 accumulators
    int i = 0;
    for (; i + 2 <= cnt; i += 2) {
        int u0 = __ldg(g_colsrc + s + i);
        int u1 = __ldg(g_colsrc + s + i + 1);
        uint2 v0 = __ldg(ep + (u0 >> 20) * 16 + sub);
        uint2 v1 = __ldg(ep + (u1 >> 20) * 16 + sub);
        hadd2(A0, v0.x); hadd2(B0, v0.y);
        hadd2(A1, v1.x); hadd2(B1, v1.y);
    }
    if (i < cnt) {
        int u = __ldg(g_colsrc + s + i);
        uint2 v = __ldg(ep + (u >> 20) * 16 + sub);
        hadd2(A0, v.x); hadd2(B0, v.y);
    }
    hadd2(A0, A1); hadd2(B0, B1);
    float inv = __fdividef(1.f, (float)max(cnt, 1));
    float2 p = h2f(A0), q = h2f(B0);
    int vid = __ldg(x + n);
    float4 r = *(const float4*)(g_Rp + vid * 64 + sub * 4);
    float4 bb = *(const float4*)(b1 + sub * 4);
    float o0 = fmaxf(fmaf(p.x, inv, r.x + bb.x), 0.f);
    float o1 = fmaxf(fmaf(p.y, inv, r.y + bb.y), 0.f);
    float o2 = fmaxf(fmaf(q.x, inv, r.z + bb.z), 0.f);
    float o3 = fmaxf(fmaf(q.y, inv, r.w + bb.w), 0.f);
    __half2 h0 = __floats2half2_rn(o0, o1);
    __half2 h1 = __floats2half2_rn(o2, o3);
    uint2 st; st.x = *(unsigned*)&h0; st.y = *(unsigned*)&h1;
    *((uint2*)g_hBh + n * 16 + sub) = st;
}

// launch 5: conv2 aggregation — warp/node, half-warp/edge, HADD2 accumulate
__global__ void k_agg(float* __restrict__ mean) {
    int n = (blockIdx.x * blockDim.x + threadIdx.x) >> 5;
    if (n >= N_NODES) return;
    int lane = threadIdx.x & 31;
    int half = lane >> 4;
    int sub = lane & 15;
    int s = g_rowptr[n], e = g_rowptr[n + 1];
    const uint2* hb = (const uint2*)g_hBh;
    unsigned A0 = 0, B0 = 0, A1 = 0, B1 = 0;
    int i = s;
    for (; i + 4 <= e; i += 4) {
        int u0 = __ldg(g_colsrc + i + half);
        int u1 = __ldg(g_colsrc + i + 2 + half);
        uint2 v0 = __ldg(hb + (u0 & 0xFFFFF) * 16 + sub);
        uint2 v1 = __ldg(hb + (u1 & 0xFFFFF) * 16 + sub);
        hadd2(A0, v0.x); hadd2(B0, v0.y);
        hadd2(A1, v1.x); hadd2(B1, v1.y);
    }
    if (i + 2 <= e) {
        int u = __ldg(g_colsrc + i + half);
        uint2 v = __ldg(hb + (u & 0xFFFFF) * 16 + sub);
        hadd2(A0, v.x); hadd2(B0, v.y);
        i += 2;
    }
    if (i < e && half == 0) {
        int u = __ldg(g_colsrc + i);
        uint2 v = __ldg(hb + (u & 0xFFFFF) * 16 + sub);
        hadd2(A0, v.x); hadd2(B0, v.y);
    }
    hadd2(A0, A1); hadd2(B0, B1);
    unsigned sa = __shfl_xor_sync(0xffffffffu, A0, 16);
    unsigned sb = __shfl_xor_sync(0xffffffffu, B0, 16);
    hadd2(A0, sa); hadd2(B0, sb);
    if (half == 0) {
        float inv = __fdividef(1.f, (float)max(e - s, 1));
        float2 p = h2f(A0), q = h2f(B0);
        float4 o; o.x = p.x * inv; o.y = p.y * inv; o.z = q.x * inv; o.w = q.y * inv;
        *(float4*)(mean + n * 64 + sub * 4) = o;
    }
}

// ---------------- launch 6: conv2 dual GEMM + bias + relu -------------------
__global__ void __launch_bounds__(256)
k_mm(const float* __restrict__ Am, const float* __restrict__ Wl,
     const float* __restrict__ Wr, const float* __restrict__ bias,
     float* __restrict__ out) {
    __shared__ ulonglong2 sWl[64 * 16];
    __shared__ ulonglong2 sWr[64 * 16];
    __shared__ u64 sB[32];
    int t = threadIdx.x;
    const ulonglong2* gWl = (const ulonglong2*)Wl;
    const ulonglong2* gWr = (const ulonglong2*)Wr;
    for (int i = t; i < 1024; i += 256) { sWl[i] = gWl[i]; sWr[i] = gWr[i]; }
    if (t < 32) sB[t] = ((const u64*)bias)[t];
    __syncthreads();
    int n = blockIdx.x * 256 + t;
    if (n >= N_NODES) return;

    u64 acc[32];
#pragma unroll
    for (int j = 0; j < 32; j++) acc[j] = sB[j];

    const float4* am4 = (const float4*)(Am + n * 64);
    const uint2*  ah2 = (const uint2*)g_hBh + n * 16;
#pragma unroll 4
    for (int k0 = 0; k0 < 16; k0++) {
        float4 a4 = __ldg(am4 + k0);
        uint2 cc = __ldg(ah2 + k0);
        float2 c01 = up2(h2f2(cc.x));
        float2 c23 = up2(h2f2(cc.y));
        float av[4] = {a4.x, a4.y, a4.z, a4.w};
        float cv[4] = {c01.x, c01.y, c23.x, c23.y};
#pragma unroll
        for (int kk = 0; kk < 4; kk++) {
            u64 a2 = pk2(av[kk]);
            u64 c2 = pk2(cv[kk]);
            const ulonglong2* wl = sWl + (k0 * 4 + kk) * 16;
            const ulonglong2* wr = sWr + (k0 * 4 + kk) * 16;
#pragma unroll
            for (int j = 0; j < 16; j++) {
                ulonglong2 l = wl[j], r = wr[j];
                fma2(acc[2 * j],     a2, l.x);
                fma2(acc[2 * j + 1], a2, l.y);
                fma2(acc[2 * j],     c2, r.x);
                fma2(acc[2 * j + 1], c2, r.y);
            }
        }
    }

    float4* o4 = (float4*)(out + n * 64);
#pragma unroll
    for (int j = 0; j < 16; j++) {
        float2 p = up2(acc[2 * j]);
        float2 q = up2(acc[2 * j + 1]);
        float4 o;
        o.x = fmaxf(p.x, 0.f); o.y = fmaxf(p.y, 0.f);
        o.z = fmaxf(q.x, 0.f); o.w = fmaxf(q.y, 0.f);
        o4[j] = o;
    }
}

// ---------------- launch 7: mean-pool + output head (warp per graph) --------
__global__ void k_pool(const float* __restrict__ h, const int* __restrict__ batch,
                       const float* __restrict__ Wout, const float* __restrict__ bout,
                       float* __restrict__ out) {
    int g = (blockIdx.x * blockDim.x + threadIdx.x) >> 5;
    if (g >= N_GRAPHS) return;
    int lane = threadIdx.x & 31;
    int s, e;
    { int lo = 0, hi = N_NODES;
      while (lo < hi) { int m = (lo + hi) >> 1; if (__ldg(batch + m) < g) lo = m + 1; else hi = m; }
      s = lo; }
    { int lo = s, hi = N_NODES;
      while (lo < hi) { int m = (lo + hi) >> 1; if (__ldg(batch + m) < g + 1) lo = m + 1; else hi = m; }
      e = lo; }
    float a0 = 0.f, a1 = 0.f;
#pragma unroll 4
    for (int n = s; n < e; ++n) {
        a0 += h[n * 64 + lane];
        a1 += h[n * 64 + lane + 32];
    }
    float inv = __fdividef(1.f, (float)max(e - s, 1));
    a0 *= inv; a1 *= inv;
    float p0 = a0 * __ldg(Wout + lane * 2 + 0) + a1 * __ldg(Wout + (lane + 32) * 2 + 0);
    float p1 = a0 * __ldg(Wout + lane * 2 + 1) + a1 * __ldg(Wout + (lane + 32) * 2 + 1);
#pragma unroll
    for (int off = 16; off; off >>= 1) {
        p0 += __shfl_xor_sync(0xffffffffu, p0, off);
        p1 += __shfl_xor_sync(0xffffffffu, p1, off);
    }
    if (lane == 0) {
        out[g * 2 + 0] = p0 + __ldg(bout + 0);
        out[g * 2 + 1] = p1 + __ldg(bout + 1);
    }
}

// ---------------- launch ----------------
extern "C" void kernel_launch(void* const* d_in, const int* in_sizes, int n_in,
                              void* d_out, int out_size) {
    const int*   x     = (const int*)d_in[0];
    const int*   ei    = (const int*)d_in[1];
    const int*   batch = (const int*)d_in[2];
    const float* emb   = (const float*)d_in[3];
    const float* W1l   = (const float*)d_in[4];
    const float* b1    = (const float*)d_in[5];
    const float* W1r   = (const float*)d_in[6];
    const float* W2l   = (const float*)d_in[7];
    const float* b2    = (const float*)d_in[8];
    const float* W2r   = (const float*)d_in[9];
    const float* Wo    = (const float*)d_in[10];
    const float* bo    = (const float*)d_in[11];
    const int* src = ei;
    const int* dst = ei + N_EDGES;
    float* out = (float*)d_out;

    float *hA, *mean;
    cudaGetSymbolAddress((void**)&hA, g_hA);
    cudaGetSymbolAddress((void**)&mean, g_mean);

    const int agg1Blocks = ((N_NODES + 1) / 2 * 32 + 255) / 256;   // 2 nodes/warp
    const int aggBlocks  = (N_NODES * 32 + 255) / 256;             // warp/node

    // 1: weight transform (E' fp16, R' fp32) + dst histogram + lb reset
    k_prep<<<128 + ((N_EDGES + 511) / 512), 256>>>(emb, W1l, W1r, dst);
    // 2: rowptr/cursor via lookback scan
    k_scanlb<<<SCAN_NB, SCAN_BS>>>();
    // 3: CSR fill, packed node|vid (+ restore deg==0)
    k_fill<<<(N_EDGES + 255) / 256, 256>>>(src, dst, x);

    // 4: conv1 fused (fp16 gather + HADD2)   <-- ncu capture slot
    k_agg1<<<agg1Blocks, 256>>>(x, b1);

    // 5-6: conv2
    k_agg<<<aggBlocks, 256>>>(mean);
    k_mm<<<(N_NODES + 255) / 256, 256>>>(mean, W2l, W2r, b2, hA);

    // 7: pool + head
    k_pool<<<(N_GRAPHS * 32 + 255) / 256, 256>>>(hA, batch, Wo, bo, out);
}

// round 12
// speedup vs baseline: 2.1961x; 1.6407x over previous
#include <cuda_runtime.h>
#include <cuda_fp16.h>

#define N_NODES 100000
#define N_EDGES 1000000
#define N_GRAPHS 2048
#define SCAN_BS 512
#define SCAN_NB ((N_NODES + SCAN_BS - 1) / SCAN_BS)
#define HISTB ((N_EDGES + 511) / 512)
#define PADN (N_NODES + 128)
// k_mmtc smem: A tile 128 x 136 halves, B tile 128 x 72 halves
#define SA_H 136
#define SB_H 72
#define SMEM_MM (128 * SA_H * 2 + 128 * SB_H * 2)

typedef unsigned long long u64;

// ---------------- device scratch (no allocs allowed) ----------------
__device__ float  g_hA[N_NODES * 64];
__device__ __half g_hBh[PADN * 64];       // conv1 output, fp16 (padded rows)
__device__ __half g_meanH[PADN * 64];     // conv2 mean, fp16 (padded rows)
__device__ __half g_EpH[128 * 64];        // emb @ W1l, fp16 (16 KB, L1-resident)
__device__ float  g_Rp[128 * 64];         // emb @ W1r, fp32
__device__ __half g_W2h[128 * 64];        // rows 0-63 = W2r, 64-127 = W2l (fp16)
__device__ int    g_deg[N_NODES];         // INVARIANT: zero at kernel_launch entry
__device__ int    g_rowptr[N_NODES + 1];
__device__ int    g_cursor[N_NODES];
__device__ int    g_colsrc[N_EDGES];      // packed: src_node | (vocab_id << 20)
__device__ u64    g_lb[SCAN_NB];

// ---------------- helpers ----------------
__device__ __forceinline__ void hadd2(unsigned &d, unsigned a) {
    asm("add.rn.f16x2 %0, %0, %1;" : "+r"(d) : "r"(a));
}
__device__ __forceinline__ float2 h2f(unsigned h) {
    __half2 v = *reinterpret_cast<__half2*>(&h);
    return __half22float2(v);
}
__device__ __forceinline__ unsigned smem_u32(const void* p) {
    unsigned a;
    asm("{ .reg .u64 t; cvta.to.shared.u64 t, %1; cvt.u32.u64 %0, t; }" : "=r"(a) : "l"(p));
    return a;
}
__device__ __forceinline__ void ldsm_x4(unsigned &r0, unsigned &r1, unsigned &r2, unsigned &r3, unsigned a) {
    asm volatile("ldmatrix.sync.aligned.m8n8.x4.shared.b16 {%0,%1,%2,%3}, [%4];"
                 : "=r"(r0), "=r"(r1), "=r"(r2), "=r"(r3) : "r"(a));
}
__device__ __forceinline__ void ldsm_x4t(unsigned &r0, unsigned &r1, unsigned &r2, unsigned &r3, unsigned a) {
    asm volatile("ldmatrix.sync.aligned.m8n8.x4.trans.shared.b16 {%0,%1,%2,%3}, [%4];"
                 : "=r"(r0), "=r"(r1), "=r"(r2), "=r"(r3) : "r"(a));
}
__device__ __forceinline__ void mma16816(float* c, unsigned a0, unsigned a1, unsigned a2, unsigned a3,
                                         unsigned b0, unsigned b1) {
    asm volatile("mma.sync.aligned.m16n8k16.row.col.f32.f16.f16.f32 "
                 "{%0,%1,%2,%3}, {%4,%5,%6,%7}, {%8,%9}, {%0,%1,%2,%3};"
                 : "+f"(c[0]), "+f"(c[1]), "+f"(c[2]), "+f"(c[3])
                 : "r"(a0), "r"(a1), "r"(a2), "r"(a3), "r"(b0), "r"(b1));
}

// -- launch 1: E'(fp16), R'(fp32) + dst histogram + W2->fp16 + lb reset ------
__global__ void k_prep(const float* __restrict__ emb, const float* __restrict__ W1l,
                       const float* __restrict__ W1r, const int* __restrict__ dst,
                       const float* __restrict__ W2l, const float* __restrict__ W2r) {
    int b = blockIdx.x, t = threadIdx.x;
    if (b < 128) {
        __shared__ float se[64];
        if (b == 0) for (int i = t; i < SCAN_NB; i += 128) g_lb[i] = 0ULL;
        if (t < 64) se[t] = emb[b * 64 + t];
        __syncthreads();
        const float* W = (t < 64) ? W1l : W1r;
        int c = t & 63;
        float acc = 0.f;
#pragma unroll 8
        for (int k = 0; k < 64; k++) acc += se[k] * __ldg(W + k * 64 + c);
        if (t < 64) g_EpH[b * 64 + c] = __float2half_rn(acc);
        else        g_Rp[b * 64 + c] = acc;
    } else if (b < 128 + HISTB) {
        int base = (b - 128) * 512;
        int e0 = base + 2 * t;
        if (e0 < N_EDGES) atomicAdd(&g_deg[__ldg(dst + e0)], 1);
        if (e0 + 1 < N_EDGES) atomicAdd(&g_deg[__ldg(dst + e0 + 1)], 1);
    } else {
        // convert W2 to fp16 concat [W2r; W2l] (8192 values over 4 blocks)
        int idx0 = (b - 128 - HISTB) * 2048 + t * 8;
#pragma unroll
        for (int i = 0; i < 8; i++) {
            int idx = idx0 + i;
            int k = idx >> 6, j = idx & 63;
            float v = (k < 64) ? __ldg(W2r + k * 64 + j) : __ldg(W2l + (k - 64) * 64 + j);
            g_W2h[idx] = __float2half_rn(v);
        }
    }
}

// ---------------- launch 2: single-pass decoupled-lookback scan -------------
__global__ void __launch_bounds__(SCAN_BS) k_scanlb() {
    __shared__ int s[SCAN_BS];
    __shared__ int s_prefix;
    int t = threadIdx.x, bid = blockIdx.x;
    int i = bid * SCAN_BS + t;
    int v = (i < N_NODES) ? g_deg[i] : 0;
    s[t] = v;
    __syncthreads();
    for (int off = 1; off < SCAN_BS; off <<= 1) {
        int x = (t >= off) ? s[t - off] : 0;
        __syncthreads();
        s[t] += x;
        __syncthreads();
    }
    int incl = s[t];
    int total = s[SCAN_BS - 1];
    if (t < 32) {
        unsigned prefix = 0;
        if (bid == 0) {
            if (t == 0) atomicExch(&g_lb[0], (2ULL << 32) | (unsigned)total);
        } else {
            if (t == 0) atomicExch(&g_lb[bid], (1ULL << 32) | (unsigned)total);
            int p = bid - 1;
            while (true) {
                int idx = p - t;
                u64 st = 0;
                if (idx >= 0) {
                    do { st = atomicAdd(&g_lb[idx], 0ULL); } while ((st >> 32) == 0);
                }
                unsigned pm = __ballot_sync(0xffffffffu, idx >= 0 && (st >> 32) == 2);
                unsigned val;
                if (pm) {
                    int closest = __ffs(pm) - 1;
                    val = (t <= closest) ? (unsigned)st : 0u;
                } else {
                    val = (idx >= 0) ? (unsigned)st : 0u;
                }
#pragma unroll
                for (int o = 16; o; o >>= 1) val += __shfl_xor_sync(0xffffffffu, val, o);
                prefix += val;
                if (pm) break;
                p -= 32;
            }
            if (t == 0) atomicExch(&g_lb[bid], (2ULL << 32) | (unsigned)(prefix + (unsigned)total));
        }
        if (t == 0) s_prefix = (int)prefix;
    }
    __syncthreads();
    int excl = incl - v + s_prefix;
    if (i < N_NODES) {
        g_rowptr[i] = excl;
        g_cursor[i] = excl;
        if (i == N_NODES - 1) g_rowptr[N_NODES] = excl + v;
    }
}

// ------- launch 3: CSR fill (packed node|vid) + restore deg invariant -------
__global__ void k_fill(const int* __restrict__ src, const int* __restrict__ dst,
                       const int* __restrict__ x) {
    int e = blockIdx.x * blockDim.x + threadIdx.x;
    if (e < N_NODES) g_deg[e] = 0;
    if (e >= N_EDGES) return;
    int sn = __ldg(src + e);
    int packed = sn | (__ldg(x + sn) << 20);
    int p = atomicAdd(&g_cursor[dst[e]], 1);
    g_colsrc[p] = packed;
}

// launch 4 [capture slot]: conv1 fused, 2 nodes/warp, fp16 gather + HADD2
__global__ void k_agg1(const int* __restrict__ x, const float* __restrict__ b1) {
    int w = (blockIdx.x * blockDim.x + threadIdx.x) >> 5;
    int lane = threadIdx.x & 31;
    int n = 2 * w + (lane >> 4);
    if (n >= N_NODES) return;
    int sub = lane & 15;
    int s = g_rowptr[n], e = g_rowptr[n + 1];
    int cnt = e - s;
    const uint2* ep = (const uint2*)g_EpH;
    unsigned A0 = 0, B0 = 0, A1 = 0, B1 = 0;
    int i = 0;
    for (; i + 2 <= cnt; i += 2) {
        int u0 = __ldg(g_colsrc + s + i);
        int u1 = __ldg(g_colsrc + s + i + 1);
        uint2 v0 = __ldg(ep + (u0 >> 20) * 16 + sub);
        uint2 v1 = __ldg(ep + (u1 >> 20) * 16 + sub);
        hadd2(A0, v0.x); hadd2(B0, v0.y);
        hadd2(A1, v1.x); hadd2(B1, v1.y);
    }
    if (i < cnt) {
        int u = __ldg(g_colsrc + s + i);
        uint2 v = __ldg(ep + (u >> 20) * 16 + sub);
        hadd2(A0, v.x); hadd2(B0, v.y);
    }
    hadd2(A0, A1); hadd2(B0, B1);
    float inv = __fdividef(1.f, (float)max(cnt, 1));
    float2 p = h2f(A0), q = h2f(B0);
    int vid = __ldg(x + n);
    float4 r = *(const float4*)(g_Rp + vid * 64 + sub * 4);
    float4 bb = *(const float4*)(b1 + sub * 4);
    float o0 = fmaxf(fmaf(p.x, inv, r.x + bb.x), 0.f);
    float o1 = fmaxf(fmaf(p.y, inv, r.y + bb.y), 0.f);
    float o2 = fmaxf(fmaf(q.x, inv, r.z + bb.z), 0.f);
    float o3 = fmaxf(fmaf(q.y, inv, r.w + bb.w), 0.f);
    __half2 h0 = __floats2half2_rn(o0, o1);
    __half2 h1 = __floats2half2_rn(o2, o3);
    uint2 st; st.x = *(unsigned*)&h0; st.y = *(unsigned*)&h1;
    *((uint2*)g_hBh + n * 16 + sub) = st;
}

// launch 5: conv2 aggregation — warp/node, half-warp/edge, HADD2, fp16 mean
__global__ void k_agg() {
    int n = (blockIdx.x * blockDim.x + threadIdx.x) >> 5;
    if (n >= N_NODES) return;
    int lane = threadIdx.x & 31;
    int half = lane >> 4;
    int sub = lane & 15;
    int s = g_rowptr[n], e = g_rowptr[n + 1];
    const uint2* hb = (const uint2*)g_hBh;
    unsigned A0 = 0, B0 = 0, A1 = 0, B1 = 0;
    int i = s;
    for (; i + 4 <= e; i += 4) {
        int u0 = __ldg(g_colsrc + i + half);
        int u1 = __ldg(g_colsrc + i + 2 + half);
        uint2 v0 = __ldg(hb + (u0 & 0xFFFFF) * 16 + sub);
        uint2 v1 = __ldg(hb + (u1 & 0xFFFFF) * 16 + sub);
        hadd2(A0, v0.x); hadd2(B0, v0.y);
        hadd2(A1, v1.x); hadd2(B1, v1.y);
    }
    if (i + 2 <= e) {
        int u = __ldg(g_colsrc + i + half);
        uint2 v = __ldg(hb + (u & 0xFFFFF) * 16 + sub);
        hadd2(A0, v.x); hadd2(B0, v.y);
        i += 2;
    }
    if (i < e && half == 0) {
        int u = __ldg(g_colsrc + i);
        uint2 v = __ldg(hb + (u & 0xFFFFF) * 16 + sub);
        hadd2(A0, v.x); hadd2(B0, v.y);
    }
    hadd2(A0, A1); hadd2(B0, B1);
    unsigned sa = __shfl_xor_sync(0xffffffffu, A0, 16);
    unsigned sb = __shfl_xor_sync(0xffffffffu, B0, 16);
    hadd2(A0, sa); hadd2(B0, sb);
    if (half == 0) {
        float inv = __fdividef(1.f, (float)max(e - s, 1));
        float2 p = h2f(A0), q = h2f(B0);
        __half2 h0 = __floats2half2_rn(p.x * inv, p.y * inv);
        __half2 h1 = __floats2half2_rn(q.x * inv, q.y * inv);
        uint2 st; st.x = *(unsigned*)&h0; st.y = *(unsigned*)&h1;
        *((uint2*)g_meanH + n * 16 + sub) = st;
    }
}

// launch 6: conv2 dual GEMM via HMMA tensor cores + bias + relu --------------
// Block = 8 warps x 16 nodes = 128 nodes. A = [hB | mean] fp16 (K=128),
// B = [W2r ; W2l] fp16 (128x64). C fp32, bias-init, relu, store fp32.
__global__ void __launch_bounds__(256)
k_mmtc(const float* __restrict__ bias, float* __restrict__ out) {
    extern __shared__ __half sm[];
    __half* sA = sm;                    // 128 x SA_H
    __half* sB = sm + 128 * SA_H;       // 128 x SB_H
    int t = threadIdx.x;
    int nbase = blockIdx.x * 128;
    // stage B (g_W2h, 128x64)
#pragma unroll
    for (int it = 0; it < 4; it++) {
        int idx = it * 256 + t;
        int row = idx >> 3, ch = idx & 7;
        uint4 v = *((const uint4*)(g_W2h + row * 64) + ch);
        *(uint4*)(sB + row * SB_H + ch * 8) = v;
    }
    // stage A: cols 0-63 = hB, 64-127 = mean (padded arrays: OOB rows harmless)
#pragma unroll
    for (int it = 0; it < 8; it++) {
        int idx = it * 256 + t;
        int row = idx >> 4, ch = idx & 15;
        uint4 v = (ch < 8)
            ? *((const uint4*)(g_hBh + (nbase + row) * 64) + ch)
            : *((const uint4*)(g_meanH + (nbase + row) * 64) + (ch - 8));
        *(uint4*)(sA + row * SA_H + ch * 8) = v;
    }
    __syncthreads();

    int w = t >> 5, lane = t & 31;
    unsigned aBase = smem_u32(sA) + ((w * 16 + (lane & 15)) * SA_H + (lane >> 4) * 8) * 2;
    unsigned bBase = smem_u32(sB) + ((lane & 15) * SB_H) * 2 + (lane >> 4) * 16;

    float c[8][4];
#pragma unroll
    for (int nt = 0; nt < 8; nt++) {
        float x0 = __ldg(bias + nt * 8 + (lane & 3) * 2);
        float x1 = __ldg(bias + nt * 8 + (lane & 3) * 2 + 1);
        c[nt][0] = x0; c[nt][1] = x1; c[nt][2] = x0; c[nt][3] = x1;
    }
#pragma unroll
    for (int kc = 0; kc < 8; kc++) {
        unsigned a0, a1, a2, a3;
        ldsm_x4(a0, a1, a2, a3, aBase + kc * 32);
#pragma unroll
        for (int j = 0; j < 4; j++) {
            unsigned b0, b1, b2, b3;
            ldsm_x4t(b0, b1, b2, b3, bBase + kc * 16 * SB_H * 2 + j * 32);
            mma16816(c[2 * j],     a0, a1, a2, a3, b0, b1);
            mma16816(c[2 * j + 1], a0, a1, a2, a3, b2, b3);
        }
    }
    int r0 = nbase + w * 16 + (lane >> 2);
    int r1 = r0 + 8;
    int cb = (lane & 3) * 2;
    bool v0 = r0 < N_NODES, v1 = r1 < N_NODES;
#pragma unroll
    for (int nt = 0; nt < 8; nt++) {
        if (v0) {
            float2 o; o.x = fmaxf(c[nt][0], 0.f); o.y = fmaxf(c[nt][1], 0.f);
            *(float2*)(out + r0 * 64 + nt * 8 + cb) = o;
        }
        if (v1) {
            float2 o; o.x = fmaxf(c[nt][2], 0.f); o.y = fmaxf(c[nt][3], 0.f);
            *(float2*)(out + r1 * 64 + nt * 8 + cb) = o;
        }
    }
}

// ---------------- launch 7: mean-pool + output head (warp per graph) --------
__global__ void k_pool(const float* __restrict__ h, const int* __restrict__ batch,
                       const float* __restrict__ Wout, const float* __restrict__ bout,
                       float* __restrict__ out) {
    int g = (blockIdx.x * blockDim.x + threadIdx.x) >> 5;
    if (g >= N_GRAPHS) return;
    int lane = threadIdx.x & 31;
    int s, e;
    { int lo = 0, hi = N_NODES;
      while (lo < hi) { int m = (lo + hi) >> 1; if (__ldg(batch + m) < g) lo = m + 1; else hi = m; }
      s = lo; }
    { int lo = s, hi = N_NODES;
      while (lo < hi) { int m = (lo + hi) >> 1; if (__ldg(batch + m) < g + 1) lo = m + 1; else hi = m; }
      e = lo; }
    float a0 = 0.f, a1 = 0.f;
#pragma unroll 4
    for (int n = s; n < e; ++n) {
        a0 += h[n * 64 + lane];
        a1 += h[n * 64 + lane + 32];
    }
    float inv = __fdividef(1.f, (float)max(e - s, 1));
    a0 *= inv; a1 *= inv;
    float p0 = a0 * __ldg(Wout + lane * 2 + 0) + a1 * __ldg(Wout + (lane + 32) * 2 + 0);
    float p1 = a0 * __ldg(Wout + lane * 2 + 1) + a1 * __ldg(Wout + (lane + 32) * 2 + 1);
#pragma unroll
    for (int off = 16; off; off >>= 1) {
        p0 += __shfl_xor_sync(0xffffffffu, p0, off);
        p1 += __shfl_xor_sync(0xffffffffu, p1, off);
    }
    if (lane == 0) {
        out[g * 2 + 0] = p0 + __ldg(bout + 0);
        out[g * 2 + 1] = p1 + __ldg(bout + 1);
    }
}

// ---------------- launch ----------------
extern "C" void kernel_launch(void* const* d_in, const int* in_sizes, int n_in,
                              void* d_out, int out_size) {
    const int*   x     = (const int*)d_in[0];
    const int*   ei    = (const int*)d_in[1];
    const int*   batch = (const int*)d_in[2];
    const float* emb   = (const float*)d_in[3];
    const float* W1l   = (const float*)d_in[4];
    const float* b1    = (const float*)d_in[5];
    const float* W1r   = (const float*)d_in[6];
    const float* W2l   = (const float*)d_in[7];
    const float* b2    = (const float*)d_in[8];
    const float* W2r   = (const float*)d_in[9];
    const float* Wo    = (const float*)d_in[10];
    const float* bo    = (const float*)d_in[11];
    const int* src = ei;
    const int* dst = ei + N_EDGES;
    float* out = (float*)d_out;

    float* hA;
    cudaGetSymbolAddress((void**)&hA, g_hA);

    static bool attr_done = false;
    if (!attr_done) {
        cudaFuncSetAttribute(k_mmtc, cudaFuncAttributeMaxDynamicSharedMemorySize, SMEM_MM);
        attr_done = true;
    }

    const int agg1Blocks = ((N_NODES + 1) / 2 * 32 + 255) / 256;   // 2 nodes/warp
    const int aggBlocks  = (N_NODES * 32 + 255) / 256;             // warp/node

    // 1: weight transforms + dst histogram + lb reset
    k_prep<<<128 + HISTB + 4, 256>>>(emb, W1l, W1r, dst, W2l, W2r);
    // 2: rowptr/cursor via lookback scan
    k_scanlb<<<SCAN_NB, SCAN_BS>>>();
    // 3: CSR fill, packed node|vid (+ restore deg==0)
    k_fill<<<(N_EDGES + 255) / 256, 256>>>(src, dst, x);

    // 4: conv1 fused (fp16 gather + HADD2)   <-- ncu capture slot (control)
    k_agg1<<<agg1Blocks, 256>>>(x, b1);

    // 5: conv2 aggregation -> fp16 mean
    k_agg<<<aggBlocks, 256>>>();
    // 6: conv2 dual GEMM on tensor cores
    k_mmtc<<<(N_NODES + 127) / 128, 256, SMEM_MM>>>(b2, hA);

    // 7: pool + head
    k_pool<<<(N_GRAPHS * 32 + 255) / 256, 256>>>(hA, batch, Wo, bo, out);
}

// round 13
// speedup vs baseline: 2.2325x; 1.0166x over previous
#include <cuda_runtime.h>
#include <cuda_fp16.h>

#define N_NODES 100000
#define N_EDGES 1000000
#define N_GRAPHS 2048
#define SCAN_BS 512
#define SCAN_NB ((N_NODES + SCAN_BS - 1) / SCAN_BS)
#define HISTB ((N_EDGES + 511) / 512)
#define PADN (N_NODES + 128)
// k_mmtc smem: A tile 128 x 136 halves, B tile 128 x 72 halves
#define SA_H 136
#define SB_H 72
#define SMEM_MM (128 * SA_H * 2 + 128 * SB_H * 2)

typedef unsigned long long u64;

// ---------------- device scratch (no allocs allowed) ----------------
__device__ float  g_hA[N_NODES * 64];
__device__ __half g_hBh[PADN * 64];       // conv1 output, fp16 (padded rows)
__device__ __half g_meanH[PADN * 64];     // conv2 mean, fp16 (padded rows)
__device__ __half g_EpH[128 * 64];        // emb @ W1l, fp16 (16 KB, L1-resident)
__device__ float  g_Rp[128 * 64];         // emb @ W1r, fp32
__device__ __half g_W2h[128 * 64];        // rows 0-63 = W2r, 64-127 = W2l (fp16)
__device__ int    g_deg[N_NODES];         // INVARIANT: zero at kernel_launch entry
__device__ int    g_rowptr[N_NODES + 1];
__device__ int    g_cursor[N_NODES];
__device__ int    g_colsrc[N_EDGES];      // packed: src_node | (vocab_id << 20)
__device__ u64    g_lb[SCAN_NB];

// ---------------- helpers ----------------
__device__ __forceinline__ void hadd2(unsigned &d, unsigned a) {
    asm("add.rn.f16x2 %0, %0, %1;" : "+r"(d) : "r"(a));
}
__device__ __forceinline__ float2 h2f(unsigned h) {
    __half2 v = *reinterpret_cast<__half2*>(&h);
    return __half22float2(v);
}
__device__ __forceinline__ unsigned smem_u32(const void* p) {
    unsigned a;
    asm("{ .reg .u64 t; cvta.to.shared.u64 t, %1; cvt.u32.u64 %0, t; }" : "=r"(a) : "l"(p));
    return a;
}
__device__ __forceinline__ void ldsm_x4(unsigned &r0, unsigned &r1, unsigned &r2, unsigned &r3, unsigned a) {
    asm volatile("ldmatrix.sync.aligned.m8n8.x4.shared.b16 {%0,%1,%2,%3}, [%4];"
                 : "=r"(r0), "=r"(r1), "=r"(r2), "=r"(r3) : "r"(a));
}
__device__ __forceinline__ void ldsm_x4t(unsigned &r0, unsigned &r1, unsigned &r2, unsigned &r3, unsigned a) {
    asm volatile("ldmatrix.sync.aligned.m8n8.x4.trans.shared.b16 {%0,%1,%2,%3}, [%4];"
                 : "=r"(r0), "=r"(r1), "=r"(r2), "=r"(r3) : "r"(a));
}
__device__ __forceinline__ void mma16816(float* c, unsigned a0, unsigned a1, unsigned a2, unsigned a3,
                                         unsigned b0, unsigned b1) {
    asm volatile("mma.sync.aligned.m16n8k16.row.col.f32.f16.f16.f32 "
                 "{%0,%1,%2,%3}, {%4,%5,%6,%7}, {%8,%9}, {%0,%1,%2,%3};"
                 : "+f"(c[0]), "+f"(c[1]), "+f"(c[2]), "+f"(c[3])
                 : "r"(a0), "r"(a1), "r"(a2), "r"(a3), "r"(b0), "r"(b1));
}

// -- launch 1: E'(fp16), R'(fp32) + dst histogram + W2->fp16 + lb reset ------
__global__ void k_prep(const float* __restrict__ emb, const float* __restrict__ W1l,
                       const float* __restrict__ W1r, const int* __restrict__ dst,
                       const float* __restrict__ W2l, const float* __restrict__ W2r) {
    int b = blockIdx.x, t = threadIdx.x;
    if (b < 128) {
        __shared__ float se[64];
        if (b == 0) for (int i = t; i < SCAN_NB; i += 128) g_lb[i] = 0ULL;
        if (t < 64) se[t] = emb[b * 64 + t];
        __syncthreads();
        const float* W = (t < 64) ? W1l : W1r;
        int c = t & 63;
        float acc = 0.f;
#pragma unroll 8
        for (int k = 0; k < 64; k++) acc += se[k] * __ldg(W + k * 64 + c);
        if (t < 64) g_EpH[b * 64 + c] = __float2half_rn(acc);
        else        g_Rp[b * 64 + c] = acc;
    } else if (b < 128 + HISTB) {
        int base = (b - 128) * 512;
        int e0 = base + 2 * t;
        if (e0 < N_EDGES) atomicAdd(&g_deg[__ldg(dst + e0)], 1);
        if (e0 + 1 < N_EDGES) atomicAdd(&g_deg[__ldg(dst + e0 + 1)], 1);
    } else {
        // convert W2 to fp16 concat [W2r; W2l] (8192 values over 4 blocks)
        int idx0 = (b - 128 - HISTB) * 2048 + t * 8;
#pragma unroll
        for (int i = 0; i < 8; i++) {
            int idx = idx0 + i;
            int k = idx >> 6, j = idx & 63;
            float v = (k < 64) ? __ldg(W2r + k * 64 + j) : __ldg(W2l + (k - 64) * 64 + j);
            g_W2h[idx] = __float2half_rn(v);
        }
    }
}

// ---------------- launch 2: single-pass decoupled-lookback scan -------------
__global__ void __launch_bounds__(SCAN_BS) k_scanlb() {
    __shared__ int s[SCAN_BS];
    __shared__ int s_prefix;
    int t = threadIdx.x, bid = blockIdx.x;
    int i = bid * SCAN_BS + t;
    int v = (i < N_NODES) ? g_deg[i] : 0;
    s[t] = v;
    __syncthreads();
    for (int off = 1; off < SCAN_BS; off <<= 1) {
        int x = (t >= off) ? s[t - off] : 0;
        __syncthreads();
        s[t] += x;
        __syncthreads();
    }
    int incl = s[t];
    int total = s[SCAN_BS - 1];
    if (t < 32) {
        unsigned prefix = 0;
        if (bid == 0) {
            if (t == 0) atomicExch(&g_lb[0], (2ULL << 32) | (unsigned)total);
        } else {
            if (t == 0) atomicExch(&g_lb[bid], (1ULL << 32) | (unsigned)total);
            int p = bid - 1;
            while (true) {
                int idx = p - t;
                u64 st = 0;
                if (idx >= 0) {
                    do { st = atomicAdd(&g_lb[idx], 0ULL); } while ((st >> 32) == 0);
                }
                unsigned pm = __ballot_sync(0xffffffffu, idx >= 0 && (st >> 32) == 2);
                unsigned val;
                if (pm) {
                    int closest = __ffs(pm) - 1;
                    val = (t <= closest) ? (unsigned)st : 0u;
                } else {
                    val = (idx >= 0) ? (unsigned)st : 0u;
                }
#pragma unroll
                for (int o = 16; o; o >>= 1) val += __shfl_xor_sync(0xffffffffu, val, o);
                prefix += val;
                if (pm) break;
                p -= 32;
            }
            if (t == 0) atomicExch(&g_lb[bid], (2ULL << 32) | (unsigned)(prefix + (unsigned)total));
        }
        if (t == 0) s_prefix = (int)prefix;
    }
    __syncthreads();
    int excl = incl - v + s_prefix;
    if (i < N_NODES) {
        g_rowptr[i] = excl;
        g_cursor[i] = excl;
        if (i == N_NODES - 1) g_rowptr[N_NODES] = excl + v;
    }
}

// ------- launch 3: CSR fill, 4 edges/thread (MLP) + restore deg invariant ---
__global__ void k_fill(const int* __restrict__ src, const int* __restrict__ dst,
                       const int* __restrict__ x) {
    int tid = blockIdx.x * blockDim.x + threadIdx.x;
    if (tid < N_NODES) g_deg[tid] = 0;
    int base = tid * 4;
    if (base >= N_EDGES) return;
    // 4 independent dependent-chains in flight
    int s0 = __ldg(src + base), s1 = __ldg(src + base + 1);
    int s2 = __ldg(src + base + 2), s3 = __ldg(src + base + 3);
    int d0 = __ldg(dst + base), d1 = __ldg(dst + base + 1);
    int d2 = __ldg(dst + base + 2), d3 = __ldg(dst + base + 3);
    int v0 = __ldg(x + s0), v1 = __ldg(x + s1);
    int v2 = __ldg(x + s2), v3 = __ldg(x + s3);
    int p0 = atomicAdd(&g_cursor[d0], 1);
    int p1 = atomicAdd(&g_cursor[d1], 1);
    int p2 = atomicAdd(&g_cursor[d2], 1);
    int p3 = atomicAdd(&g_cursor[d3], 1);
    g_colsrc[p0] = s0 | (v0 << 20);
    g_colsrc[p1] = s1 | (v1 << 20);
    g_colsrc[p2] = s2 | (v2 << 20);
    g_colsrc[p3] = s3 | (v3 << 20);
}

// launch 4 [capture slot]: conv1 fused, 2 nodes/warp, fp16 gather + HADD2
__global__ void k_agg1(const int* __restrict__ x, const float* __restrict__ b1) {
    int w = (blockIdx.x * blockDim.x + threadIdx.x) >> 5;
    int lane = threadIdx.x & 31;
    int n = 2 * w + (lane >> 4);
    if (n >= N_NODES) return;
    int sub = lane & 15;
    int s = g_rowptr[n], e = g_rowptr[n + 1];
    int cnt = e - s;
    const uint2* ep = (const uint2*)g_EpH;
    unsigned A0 = 0, B0 = 0, A1 = 0, B1 = 0;
    int i = 0;
    for (; i + 2 <= cnt; i += 2) {
        int u0 = __ldg(g_colsrc + s + i);
        int u1 = __ldg(g_colsrc + s + i + 1);
        uint2 v0 = __ldg(ep + (u0 >> 20) * 16 + sub);
        uint2 v1 = __ldg(ep + (u1 >> 20) * 16 + sub);
        hadd2(A0, v0.x); hadd2(B0, v0.y);
        hadd2(A1, v1.x); hadd2(B1, v1.y);
    }
    if (i < cnt) {
        int u = __ldg(g_colsrc + s + i);
        uint2 v = __ldg(ep + (u >> 20) * 16 + sub);
        hadd2(A0, v.x); hadd2(B0, v.y);
    }
    hadd2(A0, A1); hadd2(B0, B1);
    float inv = __fdividef(1.f, (float)max(cnt, 1));
    float2 p = h2f(A0), q = h2f(B0);
    int vid = __ldg(x + n);
    float4 r = *(const float4*)(g_Rp + vid * 64 + sub * 4);
    float4 bb = *(const float4*)(b1 + sub * 4);
    float o0 = fmaxf(fmaf(p.x, inv, r.x + bb.x), 0.f);
    float o1 = fmaxf(fmaf(p.y, inv, r.y + bb.y), 0.f);
    float o2 = fmaxf(fmaf(q.x, inv, r.z + bb.z), 0.f);
    float o3 = fmaxf(fmaf(q.y, inv, r.w + bb.w), 0.f);
    __half2 h0 = __floats2half2_rn(o0, o1);
    __half2 h1 = __floats2half2_rn(o2, o3);
    uint2 st; st.x = *(unsigned*)&h0; st.y = *(unsigned*)&h1;
    *((uint2*)g_hBh + n * 16 + sub) = st;
}

// launch 5: conv2 aggregation — 2 nodes/warp, fp16 gather + HADD2, fp16 mean
__global__ void k_agg() {
    int w = (blockIdx.x * blockDim.x + threadIdx.x) >> 5;
    int lane = threadIdx.x & 31;
    int n = 2 * w + (lane >> 4);
    if (n >= N_NODES) return;
    int sub = lane & 15;
    int s = g_rowptr[n], e = g_rowptr[n + 1];
    int cnt = e - s;
    const uint2* hb = (const uint2*)g_hBh;
    unsigned A0 = 0, B0 = 0, A1 = 0, B1 = 0;
    int i = 0;
    for (; i + 2 <= cnt; i += 2) {
        int u0 = __ldg(g_colsrc + s + i);
        int u1 = __ldg(g_colsrc + s + i + 1);
        uint2 v0 = __ldg(hb + (u0 & 0xFFFFF) * 16 + sub);
        uint2 v1 = __ldg(hb + (u1 & 0xFFFFF) * 16 + sub);
        hadd2(A0, v0.x); hadd2(B0, v0.y);
        hadd2(A1, v1.x); hadd2(B1, v1.y);
    }
    if (i < cnt) {
        int u = __ldg(g_colsrc + s + i);
        uint2 v = __ldg(hb + (u & 0xFFFFF) * 16 + sub);
        hadd2(A0, v.x); hadd2(B0, v.y);
    }
    hadd2(A0, A1); hadd2(B0, B1);
    float inv = __fdividef(1.f, (float)max(cnt, 1));
    float2 p = h2f(A0), q = h2f(B0);
    __half2 h0 = __floats2half2_rn(p.x * inv, p.y * inv);
    __half2 h1 = __floats2half2_rn(q.x * inv, q.y * inv);
    uint2 st; st.x = *(unsigned*)&h0; st.y = *(unsigned*)&h1;
    *((uint2*)g_meanH + n * 16 + sub) = st;
}

// launch 6: conv2 dual GEMM via HMMA tensor cores + bias + relu --------------
__global__ void __launch_bounds__(256)
k_mmtc(const float* __restrict__ bias, float* __restrict__ out) {
    extern __shared__ __half sm[];
    __half* sA = sm;                    // 128 x SA_H
    __half* sB = sm + 128 * SA_H;       // 128 x SB_H
    int t = threadIdx.x;
    int nbase = blockIdx.x * 128;
    // stage B (g_W2h, 128x64)
#pragma unroll
    for (int it = 0; it < 4; it++) {
        int idx = it * 256 + t;
        int row = idx >> 3, ch = idx & 7;
        uint4 v = *((const uint4*)(g_W2h + row * 64) + ch);
        *(uint4*)(sB + row * SB_H + ch * 8) = v;
    }
    // stage A: cols 0-63 = hB, 64-127 = mean (padded arrays: OOB rows harmless)
#pragma unroll
    for (int it = 0; it < 8; it++) {
        int idx = it * 256 + t;
        int row = idx >> 4, ch = idx & 15;
        uint4 v = (ch < 8)
            ? *((const uint4*)(g_hBh + (nbase + row) * 64) + ch)
            : *((const uint4*)(g_meanH + (nbase + row) * 64) + (ch - 8));
        *(uint4*)(sA + row * SA_H + ch * 8) = v;
    }
    __syncthreads();

    int w = t >> 5, lane = t & 31;
    unsigned aBase = smem_u32(sA) + ((w * 16 + (lane & 15)) * SA_H + (lane >> 4) * 8) * 2;
    unsigned bBase = smem_u32(sB) + ((lane & 15) * SB_H) * 2 + (lane >> 4) * 16;

    float c[8][4];
#pragma unroll
    for (int nt = 0; nt < 8; nt++) {
        float x0 = __ldg(bias + nt * 8 + (lane & 3) * 2);
        float x1 = __ldg(bias + nt * 8 + (lane & 3) * 2 + 1);
        c[nt][0] = x0; c[nt][1] = x1; c[nt][2] = x0; c[nt][3] = x1;
    }
#pragma unroll
    for (int kc = 0; kc < 8; kc++) {
        unsigned a0, a1, a2, a3;
        ldsm_x4(a0, a1, a2, a3, aBase + kc * 32);
#pragma unroll
        for (int j = 0; j < 4; j++) {
            unsigned b0, b1, b2, b3;
            ldsm_x4t(b0, b1, b2, b3, bBase + kc * 16 * SB_H * 2 + j * 32);
            mma16816(c[2 * j],     a0, a1, a2, a3, b0, b1);
            mma16816(c[2 * j + 1], a0, a1, a2, a3, b2, b3);
        }
    }
    int r0 = nbase + w * 16 + (lane >> 2);
    int r1 = r0 + 8;
    int cb = (lane & 3) * 2;
    bool v0 = r0 < N_NODES, v1 = r1 < N_NODES;
#pragma unroll
    for (int nt = 0; nt < 8; nt++) {
        if (v0) {
            float2 o; o.x = fmaxf(c[nt][0], 0.f); o.y = fmaxf(c[nt][1], 0.f);
            *(float2*)(out + r0 * 64 + nt * 8 + cb) = o;
        }
        if (v1) {
            float2 o; o.x = fmaxf(c[nt][2], 0.f); o.y = fmaxf(c[nt][3], 0.f);
            *(float2*)(out + r1 * 64 + nt * 8 + cb) = o;
        }
    }
}

// ---------------- launch 7: mean-pool + output head (warp per graph) --------
__global__ void k_pool(const float* __restrict__ h, const int* __restrict__ batch,
                       const float* __restrict__ Wout, const float* __restrict__ bout,
                       float* __restrict__ out) {
    int g = (blockIdx.x * blockDim.x + threadIdx.x) >> 5;
    if (g >= N_GRAPHS) return;
    int lane = threadIdx.x & 31;
    int s, e;
    { int lo = 0, hi = N_NODES;
      while (lo < hi) { int m = (lo + hi) >> 1; if (__ldg(batch + m) < g) lo = m + 1; else hi = m; }
      s = lo; }
    { int lo = s, hi = N_NODES;
      while (lo < hi) { int m = (lo + hi) >> 1; if (__ldg(batch + m) < g + 1) lo = m + 1; else hi = m; }
      e = lo; }
    float a0 = 0.f, a1 = 0.f;
#pragma unroll 4
    for (int n = s; n < e; ++n) {
        a0 += h[n * 64 + lane];
        a1 += h[n * 64 + lane + 32];
    }
    float inv = __fdividef(1.f, (float)max(e - s, 1));
    a0 *= inv; a1 *= inv;
    float p0 = a0 * __ldg(Wout + lane * 2 + 0) + a1 * __ldg(Wout + (lane + 32) * 2 + 0);
    float p1 = a0 * __ldg(Wout + lane * 2 + 1) + a1 * __ldg(Wout + (lane + 32) * 2 + 1);
#pragma unroll
    for (int off = 16; off; off >>= 1) {
        p0 += __shfl_xor_sync(0xffffffffu, p0, off);
        p1 += __shfl_xor_sync(0xffffffffu, p1, off);
    }
    if (lane == 0) {
        out[g * 2 + 0] = p0 + __ldg(bout + 0);
        out[g * 2 + 1] = p1 + __ldg(bout + 1);
    }
}

// ---------------- launch ----------------
extern "C" void kernel_launch(void* const* d_in, const int* in_sizes, int n_in,
                              void* d_out, int out_size) {
    const int*   x     = (const int*)d_in[0];
    const int*   ei    = (const int*)d_in[1];
    const int*   batch = (const int*)d_in[2];
    const float* emb   = (const float*)d_in[3];
    const float* W1l   = (const float*)d_in[4];
    const float* b1    = (const float*)d_in[5];
    const float* W1r   = (const float*)d_in[6];
    const float* W2l   = (const float*)d_in[7];
    const float* b2    = (const float*)d_in[8];
    const float* W2r   = (const float*)d_in[9];
    const float* Wo    = (const float*)d_in[10];
    const float* bo    = (const float*)d_in[11];
    const int* src = ei;
    const int* dst = ei + N_EDGES;
    float* out = (float*)d_out;

    float* hA;
    cudaGetSymbolAddress((void**)&hA, g_hA);

    static bool attr_done = false;
    if (!attr_done) {
        cudaFuncSetAttribute(k_mmtc, cudaFuncAttributeMaxDynamicSharedMemorySize, SMEM_MM);
        attr_done = true;
    }

    const int aggBlocks = ((N_NODES + 1) / 2 * 32 + 255) / 256;   // 2 nodes/warp

    // 1: weight transforms + dst histogram + lb reset
    k_prep<<<128 + HISTB + 4, 256>>>(emb, W1l, W1r, dst, W2l, W2r);
    // 2: rowptr/cursor via lookback scan
    k_scanlb<<<SCAN_NB, SCAN_BS>>>();
    // 3: CSR fill, 4 edges/thread (+ restore deg==0)
    k_fill<<<(N_EDGES / 4 + 255) / 256, 256>>>(src, dst, x);

    // 4: conv1 fused (fp16 gather + HADD2)   <-- ncu capture slot (control)
    k_agg1<<<aggBlocks, 256>>>(x, b1);

    // 5: conv2 aggregation -> fp16 mean (2 nodes/warp)
    k_agg<<<aggBlocks, 256>>>();
    // 6: conv2 dual GEMM on tensor cores
    k_mmtc<<<(N_NODES + 127) / 128, 256, SMEM_MM>>>(b2, hA);

    // 7: pool + head
    k_pool<<<(N_GRAPHS * 32 + 255) / 256, 256>>>(hA, batch, Wo, bo, out);
}

// round 14
// speedup vs baseline: 2.3944x; 1.0725x over previous
#include <cuda_runtime.h>
#include <cuda_fp16.h>

#define N_NODES 100000
#define N_EDGES 1000000
#define N_GRAPHS 2048
#define SCAN_BS 512
#define SCAN_NB ((N_NODES + SCAN_BS - 1) / SCAN_BS)
#define HISTB ((N_EDGES + 1023) / 1024)
#define PADN (N_NODES + 128)
// k_mmtc smem: A tile 128 x 136 halves, B tile 128 x 72 halves
#define SA_H 136
#define SB_H 72
#define SMEM_MM (128 * SA_H * 2 + 128 * SB_H * 2)

typedef unsigned long long u64;

// ---------------- device scratch (no allocs allowed) ----------------
__device__ float  g_hA[N_NODES * 64];
__device__ __half g_hBh[PADN * 64];       // conv1 output, fp16 (padded rows)
__device__ __half g_meanH[PADN * 64];     // conv2 mean, fp16 (padded rows)
__device__ __half g_EpH[128 * 64];        // emb @ W1l, fp16 (16 KB, L1-resident)
__device__ float  g_Rp[128 * 64];         // emb @ W1r, fp32
__device__ __half g_W2h[128 * 64];        // rows 0-63 = W2r, 64-127 = W2l (fp16)
__device__ int    g_deg[N_NODES];         // INVARIANT: zero at kernel_launch entry
__device__ int    g_rowptr[N_NODES + 1];
__device__ int    g_cursor[N_NODES];
__device__ int    g_colsrc[N_EDGES];      // packed: src_node | (vocab_id << 20)
__device__ int    g_gstart[N_GRAPHS + 1]; // graph -> first node index (batch sorted)
__device__ u64    g_lb[SCAN_NB];

// ---------------- helpers ----------------
__device__ __forceinline__ void hadd2(unsigned &d, unsigned a) {
    asm("add.rn.f16x2 %0, %0, %1;" : "+r"(d) : "r"(a));
}
__device__ __forceinline__ float2 h2f(unsigned h) {
    __half2 v = *reinterpret_cast<__half2*>(&h);
    return __half22float2(v);
}
__device__ __forceinline__ unsigned smem_u32(const void* p) {
    unsigned a;
    asm("{ .reg .u64 t; cvta.to.shared.u64 t, %1; cvt.u32.u64 %0, t; }" : "=r"(a) : "l"(p));
    return a;
}
__device__ __forceinline__ void ldsm_x4(unsigned &r0, unsigned &r1, unsigned &r2, unsigned &r3, unsigned a) {
    asm volatile("ldmatrix.sync.aligned.m8n8.x4.shared.b16 {%0,%1,%2,%3}, [%4];"
                 : "=r"(r0), "=r"(r1), "=r"(r2), "=r"(r3) : "r"(a));
}
__device__ __forceinline__ void ldsm_x4t(unsigned &r0, unsigned &r1, unsigned &r2, unsigned &r3, unsigned a) {
    asm volatile("ldmatrix.sync.aligned.m8n8.x4.trans.shared.b16 {%0,%1,%2,%3}, [%4];"
                 : "=r"(r0), "=r"(r1), "=r"(r2), "=r"(r3) : "r"(a));
}
__device__ __forceinline__ void mma16816(float* c, unsigned a0, unsigned a1, unsigned a2, unsigned a3,
                                         unsigned b0, unsigned b1) {
    asm volatile("mma.sync.aligned.m16n8k16.row.col.f32.f16.f16.f32 "
                 "{%0,%1,%2,%3}, {%4,%5,%6,%7}, {%8,%9}, {%0,%1,%2,%3};"
                 : "+f"(c[0]), "+f"(c[1]), "+f"(c[2]), "+f"(c[3])
                 : "r"(a0), "r"(a1), "r"(a2), "r"(a3), "r"(b0), "r"(b1));
}

// -- launch 1: E'(fp16), R'(fp32) + dst histogram(int4) + W2->fp16 + lb reset -
__global__ void k_prep(const float* __restrict__ emb, const float* __restrict__ W1l,
                       const float* __restrict__ W1r, const int* __restrict__ dst,
                       const float* __restrict__ W2l, const float* __restrict__ W2r) {
    int b = blockIdx.x, t = threadIdx.x;
    if (b < 128) {
        __shared__ float se[64];
        if (b == 0) for (int i = t; i < SCAN_NB; i += 128) g_lb[i] = 0ULL;
        if (t < 64) se[t] = emb[b * 64 + t];
        __syncthreads();
        const float* W = (t < 64) ? W1l : W1r;
        int c = t & 63;
        float acc = 0.f;
#pragma unroll 8
        for (int k = 0; k < 64; k++) acc += se[k] * __ldg(W + k * 64 + c);
        if (t < 64) g_EpH[b * 64 + c] = __float2half_rn(acc);
        else        g_Rp[b * 64 + c] = acc;
    } else if (b < 128 + HISTB) {
        int base = (b - 128) * 1024 + t * 4;
        if (base < N_EDGES) {
            int4 d = *(const int4*)(dst + base);
            atomicAdd(&g_deg[d.x], 1);
            atomicAdd(&g_deg[d.y], 1);
            atomicAdd(&g_deg[d.z], 1);
            atomicAdd(&g_deg[d.w], 1);
        }
    } else {
        // convert W2 to fp16 concat [W2r; W2l] (8192 values over 4 blocks)
        int idx0 = (b - 128 - HISTB) * 2048 + t * 8;
#pragma unroll
        for (int i = 0; i < 8; i++) {
            int idx = idx0 + i;
            int k = idx >> 6, j = idx & 63;
            float v = (k < 64) ? __ldg(W2r + k * 64 + j) : __ldg(W2l + (k - 64) * 64 + j);
            g_W2h[idx] = __float2half_rn(v);
        }
    }
}

// ---------------- launch 2: single-pass decoupled-lookback scan -------------
__global__ void __launch_bounds__(SCAN_BS) k_scanlb() {
    __shared__ int s[SCAN_BS];
    __shared__ int s_prefix;
    int t = threadIdx.x, bid = blockIdx.x;
    int i = bid * SCAN_BS + t;
    int v = (i < N_NODES) ? g_deg[i] : 0;
    s[t] = v;
    __syncthreads();
    for (int off = 1; off < SCAN_BS; off <<= 1) {
        int x = (t >= off) ? s[t - off] : 0;
        __syncthreads();
        s[t] += x;
        __syncthreads();
    }
    int incl = s[t];
    int total = s[SCAN_BS - 1];
    if (t < 32) {
        unsigned prefix = 0;
        if (bid == 0) {
            if (t == 0) atomicExch(&g_lb[0], (2ULL << 32) | (unsigned)total);
        } else {
            if (t == 0) atomicExch(&g_lb[bid], (1ULL << 32) | (unsigned)total);
            int p = bid - 1;
            while (true) {
                int idx = p - t;
                u64 st = 0;
                if (idx >= 0) {
                    do { st = atomicAdd(&g_lb[idx], 0ULL); } while ((st >> 32) == 0);
                }
                unsigned pm = __ballot_sync(0xffffffffu, idx >= 0 && (st >> 32) == 2);
                unsigned val;
                if (pm) {
                    int closest = __ffs(pm) - 1;
                    val = (t <= closest) ? (unsigned)st : 0u;
                } else {
                    val = (idx >= 0) ? (unsigned)st : 0u;
                }
#pragma unroll
                for (int o = 16; o; o >>= 1) val += __shfl_xor_sync(0xffffffffu, val, o);
                prefix += val;
                if (pm) break;
                p -= 32;
            }
            if (t == 0) atomicExch(&g_lb[bid], (2ULL << 32) | (unsigned)(prefix + (unsigned)total));
        }
        if (t == 0) s_prefix = (int)prefix;
    }
    __syncthreads();
    int excl = incl - v + s_prefix;
    if (i < N_NODES) {
        g_rowptr[i] = excl;
        g_cursor[i] = excl;
        if (i == N_NODES - 1) g_rowptr[N_NODES] = excl + v;
    }
}

// --- launch 3: CSR fill (4 edges/thread) + deg reset + graph-start table ----
__global__ void k_fill(const int* __restrict__ src, const int* __restrict__ dst,
                       const int* __restrict__ x, const int* __restrict__ batch) {
    int tid = blockIdx.x * blockDim.x + threadIdx.x;
    if (tid < N_NODES) {
        g_deg[tid] = 0;
        int b = __ldg(batch + tid);
        int bprev = (tid == 0) ? -1 : __ldg(batch + tid - 1);
        for (int g = bprev + 1; g <= b; g++) g_gstart[g] = tid;
        if (tid == N_NODES - 1)
            for (int g = b + 1; g <= N_GRAPHS; g++) g_gstart[g] = N_NODES;
    }
    int base = tid * 4;
    if (base >= N_EDGES) return;
    int s0 = __ldg(src + base), s1 = __ldg(src + base + 1);
    int s2 = __ldg(src + base + 2), s3 = __ldg(src + base + 3);
    int d0 = __ldg(dst + base), d1 = __ldg(dst + base + 1);
    int d2 = __ldg(dst + base + 2), d3 = __ldg(dst + base + 3);
    int v0 = __ldg(x + s0), v1 = __ldg(x + s1);
    int v2 = __ldg(x + s2), v3 = __ldg(x + s3);
    int p0 = atomicAdd(&g_cursor[d0], 1);
    int p1 = atomicAdd(&g_cursor[d1], 1);
    int p2 = atomicAdd(&g_cursor[d2], 1);
    int p3 = atomicAdd(&g_cursor[d3], 1);
    g_colsrc[p0] = s0 | (v0 << 20);
    g_colsrc[p1] = s1 | (v1 << 20);
    g_colsrc[p2] = s2 | (v2 << 20);
    g_colsrc[p3] = s3 | (v3 << 20);
}

// launch 4 [capture slot]: conv1 fused, 2 nodes/warp, fp16 gather + HADD2, x4 unroll
__global__ void k_agg1(const int* __restrict__ x, const float* __restrict__ b1) {
    int w = (blockIdx.x * blockDim.x + threadIdx.x) >> 5;
    int lane = threadIdx.x & 31;
    int n = 2 * w + (lane >> 4);
    if (n >= N_NODES) return;
    int sub = lane & 15;
    int s = g_rowptr[n], e = g_rowptr[n + 1];
    int cnt = e - s;
    const uint2* ep = (const uint2*)g_EpH;
    unsigned A0 = 0, B0 = 0, A1 = 0, B1 = 0;
    int i = 0;
    for (; i + 4 <= cnt; i += 4) {
        int u0 = __ldg(g_colsrc + s + i);
        int u1 = __ldg(g_colsrc + s + i + 1);
        int u2 = __ldg(g_colsrc + s + i + 2);
        int u3 = __ldg(g_colsrc + s + i + 3);
        uint2 v0 = __ldg(ep + (u0 >> 20) * 16 + sub);
        uint2 v1 = __ldg(ep + (u1 >> 20) * 16 + sub);
        uint2 v2 = __ldg(ep + (u2 >> 20) * 16 + sub);
        uint2 v3 = __ldg(ep + (u3 >> 20) * 16 + sub);
        hadd2(A0, v0.x); hadd2(B0, v0.y);
        hadd2(A1, v1.x); hadd2(B1, v1.y);
        hadd2(A0, v2.x); hadd2(B0, v2.y);
        hadd2(A1, v3.x); hadd2(B1, v3.y);
    }
    if (i + 2 <= cnt) {
        int u0 = __ldg(g_colsrc + s + i);
        int u1 = __ldg(g_colsrc + s + i + 1);
        uint2 v0 = __ldg(ep + (u0 >> 20) * 16 + sub);
        uint2 v1 = __ldg(ep + (u1 >> 20) * 16 + sub);
        hadd2(A0, v0.x); hadd2(B0, v0.y);
        hadd2(A1, v1.x); hadd2(B1, v1.y);
        i += 2;
    }
    if (i < cnt) {
        int u = __ldg(g_colsrc + s + i);
        uint2 v = __ldg(ep + (u >> 20) * 16 + sub);
        hadd2(A0, v.x); hadd2(B0, v.y);
    }
    hadd2(A0, A1); hadd2(B0, B1);
    float inv = __fdividef(1.f, (float)max(cnt, 1));
    float2 p = h2f(A0), q = h2f(B0);
    int vid = __ldg(x + n);
    float4 r = *(const float4*)(g_Rp + vid * 64 + sub * 4);
    float4 bb = *(const float4*)(b1 + sub * 4);
    float o0 = fmaxf(fmaf(p.x, inv, r.x + bb.x), 0.f);
    float o1 = fmaxf(fmaf(p.y, inv, r.y + bb.y), 0.f);
    float o2 = fmaxf(fmaf(q.x, inv, r.z + bb.z), 0.f);
    float o3 = fmaxf(fmaf(q.y, inv, r.w + bb.w), 0.f);
    __half2 h0 = __floats2half2_rn(o0, o1);
    __half2 h1 = __floats2half2_rn(o2, o3);
    uint2 st; st.x = *(unsigned*)&h0; st.y = *(unsigned*)&h1;
    *((uint2*)g_hBh + n * 16 + sub) = st;
}

// launch 5: conv2 aggregation — 2 nodes/warp, fp16 gather + HADD2, x4 unroll
__global__ void k_agg() {
    int w = (blockIdx.x * blockDim.x + threadIdx.x) >> 5;
    int lane = threadIdx.x & 31;
    int n = 2 * w + (lane >> 4);
    if (n >= N_NODES) return;
    int sub = lane & 15;
    int s = g_rowptr[n], e = g_rowptr[n + 1];
    int cnt = e - s;
    const uint2* hb = (const uint2*)g_hBh;
    unsigned A0 = 0, B0 = 0, A1 = 0, B1 = 0;
    int i = 0;
    for (; i + 4 <= cnt; i += 4) {
        int u0 = __ldg(g_colsrc + s + i);
        int u1 = __ldg(g_colsrc + s + i + 1);
        int u2 = __ldg(g_colsrc + s + i + 2);
        int u3 = __ldg(g_colsrc + s + i + 3);
        uint2 v0 = __ldg(hb + (u0 & 0xFFFFF) * 16 + sub);
        uint2 v1 = __ldg(hb + (u1 & 0xFFFFF) * 16 + sub);
        uint2 v2 = __ldg(hb + (u2 & 0xFFFFF) * 16 + sub);
        uint2 v3 = __ldg(hb + (u3 & 0xFFFFF) * 16 + sub);
        hadd2(A0, v0.x); hadd2(B0, v0.y);
        hadd2(A1, v1.x); hadd2(B1, v1.y);
        hadd2(A0, v2.x); hadd2(B0, v2.y);
        hadd2(A1, v3.x); hadd2(B1, v3.y);
    }
    if (i + 2 <= cnt) {
        int u0 = __ldg(g_colsrc + s + i);
        int u1 = __ldg(g_colsrc + s + i + 1);
        uint2 v0 = __ldg(hb + (u0 & 0xFFFFF) * 16 + sub);
        uint2 v1 = __ldg(hb + (u1 & 0xFFFFF) * 16 + sub);
        hadd2(A0, v0.x); hadd2(B0, v0.y);
        hadd2(A1, v1.x); hadd2(B1, v1.y);
        i += 2;
    }
    if (i < cnt) {
        int u = __ldg(g_colsrc + s + i);
        uint2 v = __ldg(hb + (u & 0xFFFFF) * 16 + sub);
        hadd2(A0, v.x); hadd2(B0, v.y);
    }
    hadd2(A0, A1); hadd2(B0, B1);
    float inv = __fdividef(1.f, (float)max(cnt, 1));
    float2 p = h2f(A0), q = h2f(B0);
    __half2 h0 = __floats2half2_rn(p.x * inv, p.y * inv);
    __half2 h1 = __floats2half2_rn(q.x * inv, q.y * inv);
    uint2 st; st.x = *(unsigned*)&h0; st.y = *(unsigned*)&h1;
    *((uint2*)g_meanH + n * 16 + sub) = st;
}

// launch 6: conv2 dual GEMM via HMMA tensor cores + bias + relu --------------
__global__ void __launch_bounds__(256)
k_mmtc(const float* __restrict__ bias, float* __restrict__ out) {
    extern __shared__ __half sm[];
    __half* sA = sm;                    // 128 x SA_H
    __half* sB = sm + 128 * SA_H;       // 128 x SB_H
    int t = threadIdx.x;
    int nbase = blockIdx.x * 128;
#pragma unroll
    for (int it = 0; it < 4; it++) {
        int idx = it * 256 + t;
        int row = idx >> 3, ch = idx & 7;
        uint4 v = *((const uint4*)(g_W2h + row * 64) + ch);
        *(uint4*)(sB + row * SB_H + ch * 8) = v;
    }
#pragma unroll
    for (int it = 0; it < 8; it++) {
        int idx = it * 256 + t;
        int row = idx >> 4, ch = idx & 15;
        uint4 v = (ch < 8)
            ? *((const uint4*)(g_hBh + (nbase + row) * 64) + ch)
            : *((const uint4*)(g_meanH + (nbase + row) * 64) + (ch - 8));
        *(uint4*)(sA + row * SA_H + ch * 8) = v;
    }
    __syncthreads();

    int w = t >> 5, lane = t & 31;
    unsigned aBase = smem_u32(sA) + ((w * 16 + (lane & 15)) * SA_H + (lane >> 4) * 8) * 2;
    unsigned bBase = smem_u32(sB) + ((lane & 15) * SB_H) * 2 + (lane >> 4) * 16;

    float c[8][4];
#pragma unroll
    for (int nt = 0; nt < 8; nt++) {
        float x0 = __ldg(bias + nt * 8 + (lane & 3) * 2);
        float x1 = __ldg(bias + nt * 8 + (lane & 3) * 2 + 1);
        c[nt][0] = x0; c[nt][1] = x1; c[nt][2] = x0; c[nt][3] = x1;
    }
#pragma unroll
    for (int kc = 0; kc < 8; kc++) {
        unsigned a0, a1, a2, a3;
        ldsm_x4(a0, a1, a2, a3, aBase + kc * 32);
#pragma unroll
        for (int j = 0; j < 4; j++) {
            unsigned b0, b1, b2, b3;
            ldsm_x4t(b0, b1, b2, b3, bBase + kc * 16 * SB_H * 2 + j * 32);
            mma16816(c[2 * j],     a0, a1, a2, a3, b0, b1);
            mma16816(c[2 * j + 1], a0, a1, a2, a3, b2, b3);
        }
    }
    int r0 = nbase + w * 16 + (lane >> 2);
    int r1 = r0 + 8;
    int cb = (lane & 3) * 2;
    bool v0 = r0 < N_NODES, v1 = r1 < N_NODES;
#pragma unroll
    for (int nt = 0; nt < 8; nt++) {
        if (v0) {
            float2 o; o.x = fmaxf(c[nt][0], 0.f); o.y = fmaxf(c[nt][1], 0.f);
            *(float2*)(out + r0 * 64 + nt * 8 + cb) = o;
        }
        if (v1) {
            float2 o; o.x = fmaxf(c[nt][2], 0.f); o.y = fmaxf(c[nt][3], 0.f);
            *(float2*)(out + r1 * 64 + nt * 8 + cb) = o;
        }
    }
}

// ---- launch 7: mean-pool + output head (warp per graph, gstart table) ------
__global__ void k_pool(const float* __restrict__ h,
                       const float* __restrict__ Wout, const float* __restrict__ bout,
                       float* __restrict__ out) {
    int g = (blockIdx.x * blockDim.x + threadIdx.x) >> 5;
    if (g >= N_GRAPHS) return;
    int lane = threadIdx.x & 31;
    int s = g_gstart[g], e = g_gstart[g + 1];
    float a0 = 0.f, a1 = 0.f, b0 = 0.f, b1 = 0.f;
    int n = s;
    for (; n + 2 <= e; n += 2) {
        a0 += __ldg(h + n * 64 + lane);
        a1 += __ldg(h + n * 64 + lane + 32);
        b0 += __ldg(h + (n + 1) * 64 + lane);
        b1 += __ldg(h + (n + 1) * 64 + lane + 32);
    }
    if (n < e) {
        a0 += __ldg(h + n * 64 + lane);
        a1 += __ldg(h + n * 64 + lane + 32);
    }
    a0 += b0; a1 += b1;
    float inv = __fdividef(1.f, (float)max(e - s, 1));
    a0 *= inv; a1 *= inv;
    float p0 = a0 * __ldg(Wout + lane * 2 + 0) + a1 * __ldg(Wout + (lane + 32) * 2 + 0);
    float p1 = a0 * __ldg(Wout + lane * 2 + 1) + a1 * __ldg(Wout + (lane + 32) * 2 + 1);
#pragma unroll
    for (int off = 16; off; off >>= 1) {
        p0 += __shfl_xor_sync(0xffffffffu, p0, off);
        p1 += __shfl_xor_sync(0xffffffffu, p1, off);
    }
    if (lane == 0) {
        out[g * 2 + 0] = p0 + __ldg(bout + 0);
        out[g * 2 + 1] = p1 + __ldg(bout + 1);
    }
}

// ---------------- launch ----------------
extern "C" void kernel_launch(void* const* d_in, const int* in_sizes, int n_in,
                              void* d_out, int out_size) {
    const int*   x     = (const int*)d_in[0];
    const int*   ei    = (const int*)d_in[1];
    const int*   batch = (const int*)d_in[2];
    const float* emb   = (const float*)d_in[3];
    const float* W1l   = (const float*)d_in[4];
    const float* b1    = (const float*)d_in[5];
    const float* W1r   = (const float*)d_in[6];
    const float* W2l   = (const float*)d_in[7];
    const float* b2    = (const float*)d_in[8];
    const float* W2r   = (const float*)d_in[9];
    const float* Wo    = (const float*)d_in[10];
    const float* bo    = (const float*)d_in[11];
    const int* src = ei;
    const int* dst = ei + N_EDGES;
    float* out = (float*)d_out;

    float* hA;
    cudaGetSymbolAddress((void**)&hA, g_hA);

    static bool attr_done = false;
    if (!attr_done) {
        cudaFuncSetAttribute(k_mmtc, cudaFuncAttributeMaxDynamicSharedMemorySize, SMEM_MM);
        attr_done = true;
    }

    const int aggBlocks = ((N_NODES + 1) / 2 * 32 + 255) / 256;   // 2 nodes/warp

    // 1: weight transforms + dst histogram + lb reset
    k_prep<<<128 + HISTB + 4, 256>>>(emb, W1l, W1r, dst, W2l, W2r);
    // 2: rowptr/cursor via lookback scan
    k_scanlb<<<SCAN_NB, SCAN_BS>>>();
    // 3: CSR fill (4 edges/thread) + deg reset + gstart table
    k_fill<<<(N_EDGES / 4 + 255) / 256, 256>>>(src, dst, x, batch);

    // 4: conv1 fused (fp16 gather + HADD2)   <-- ncu capture slot
    k_agg1<<<aggBlocks, 256>>>(x, b1);

    // 5: conv2 aggregation -> fp16 mean (2 nodes/warp)
    k_agg<<<aggBlocks, 256>>>();
    // 6: conv2 dual GEMM on tensor cores
    k_mmtc<<<(N_NODES + 127) / 128, 256, SMEM_MM>>>(b2, hA);

    // 7: pool + head (gstart table, no binary search)
    k_pool<<<(N_GRAPHS * 32 + 255) / 256, 256>>>(hA, Wo, bo, out);
}